// round 10
// baseline (speedup 1.0000x reference)
#include <cuda_runtime.h>
#include <cuda_bf16.h>
#include <cstdint>

// ---------------- problem constants ----------------
#define B_      2
#define NPIX    576
#define NL      171
#define NBL     342
#define NPAD    384
#define ICH     768
#define OC1     512
#define OC2     512
#define K1      768
#define K2      4608
#define KSPLIT  12
#define IMG_ELEMS  (577*B_*768)
#define TXT_ELEMS  (B_*77*NL*512)

// pixel classes: interior rows/cols = [5,18] (14), edge = 10
#define BX_ROWS 1344
#define AROWS   8192
#define P_II_OFF 0
#define P_EI_OFF 229376
#define P_IE_OFF 720896
#define P_EE_OFF 1212416
#define P_TOTAL  2392064

// ---------------- scratch ----------------
__device__ __align__(128) __nv_bfloat16 g_Aall[(size_t)AROWS * K1];
__device__ __align__(128) __nv_bfloat16 g_Bx2[(size_t)BX_ROWS * K1];
__device__ __align__(128) __nv_bfloat16 g_Pcat[P_TOTAL];
__device__ __align__(128) __nv_bfloat16 g_W2b[OC2 * K2];
__device__ __align__(128) __nv_bfloat16 g_Tbb[NPAD * K2];
__device__ __align__(128) float         g_part[KSPLIT * NPAD * OC2];
__device__ int g_m[B_ * NPIX];

// ---------------- PTX helpers ----------------
__device__ __forceinline__ uint32_t smem_u32(const void* p) {
    uint32_t a;
    asm("{ .reg .u64 t; cvta.to.shared.u64 t, %1; cvt.u32.u64 %0, t; }" : "=r"(a) : "l"(p));
    return a;
}
__device__ __forceinline__ void cpasync16(uint32_t dst, const void* src) {
    asm volatile("cp.async.cg.shared.global [%0], [%1], 16;\n" :: "r"(dst), "l"(src));
}
#define CP_COMMIT() asm volatile("cp.async.commit_group;\n" ::: "memory")

__device__ __forceinline__ void ldsm_x4(uint32_t& r0, uint32_t& r1, uint32_t& r2,
                                        uint32_t& r3, uint32_t addr) {
    asm volatile("ldmatrix.sync.aligned.m8n8.x4.shared.b16 {%0,%1,%2,%3}, [%4];"
                 : "=r"(r0), "=r"(r1), "=r"(r2), "=r"(r3) : "r"(addr));
}
__device__ __forceinline__ void mma_bf16(float* c, const uint32_t* a, const uint32_t* b) {
    asm volatile("mma.sync.aligned.m16n8k16.row.col.f32.bf16.bf16.f32 "
                 "{%0,%1,%2,%3}, {%4,%5,%6,%7}, {%8,%9}, {%0,%1,%2,%3};"
                 : "+f"(c[0]), "+f"(c[1]), "+f"(c[2]), "+f"(c[3])
                 : "r"(a[0]), "r"(a[1]), "r"(a[2]), "r"(a[3]), "r"(b[0]), "r"(b[1]));
}
__device__ __forceinline__ void store_c(float* p, float v) { *p = v; }
__device__ __forceinline__ void store_c(__nv_bfloat16* p, float v) { *p = __float2bfloat16(v); }

// pixel -> B-matrix row (class-sorted layout)
__device__ __forceinline__ int browmap(int b, int pix) {
    int p = pix / 24, q = pix % 24;
    bool Ip = (p >= 5 && p <= 18), Iq = (q >= 5 && q <= 18);
    int rep = (p < 5) ? p : p - 14;
    int req = (q < 5) ? q : q - 14;
    if (Ip && Iq)  return        b * 196 + (p - 5) * 14 + (q - 5);
    if (!Ip && Iq) return 448 +  b * 140 + rep * 14 + (q - 5);
    if (Ip)        return 768 +  b * 140 + (p - 5) * 10 + req;
    return 1088 + b * 100 + rep * 10 + req;
}

// ---------------- labels ----------------
__global__ void labels_k(const int* __restrict__ targets) {
    int i = blockIdx.x * blockDim.x + threadIdx.x;
    if (i >= B_ * NPIX) return;
    int b = i / NPIX, pix = i % NPIX;
    int pi = pix / 24, qj = pix % 24;
    g_m[i] = targets[b * 147456 + (pi * 16) * 384 + qj * 16];
}

// ---------------- fused prep A: xpack (864 blocks) + weight build (512 blocks) ----------------
#define XPACK_BLOCKS (18 * 24 * 2)
__global__ __launch_bounds__(256) void prepA_k(const float* __restrict__ noise,
                                               const float* __restrict__ w1) {
    int bid = blockIdx.x;
    if (bid < XPACK_BLOCKS) {
        __shared__ float tile[32][33];
        int b = bid / (18 * 24);
        int r0 = bid % (18 * 24);
        int p0 = (r0 % 18) * 32, c0 = (r0 / 18) * 32;
        int tx = threadIdx.x & 31, ty = threadIdx.x >> 5;
        for (int r = ty; r < 32; r += 8)
            tile[r][tx] = noise[(size_t)b * 443136 + (c0 + r) * 577 + 1 + p0 + tx];
        __syncthreads();
        for (int r = ty; r < 32; r += 8) {
            int dstrow = browmap(b, p0 + r);
            g_Bx2[(size_t)dstrow * K1 + c0 + tx] = __float2bfloat16(tile[tx][r]);
        }
    } else {
        __shared__ float sm[ICH * 9];
        int oc1 = bid - XPACK_BLOCKS;
        const float4* src = (const float4*)(w1 + (size_t)oc1 * ICH * 9);
        for (int i = threadIdx.x; i < ICH * 9 / 4; i += 256)
            ((float4*)sm)[i] = src[i];
        __syncthreads();
        for (int ic = threadIdx.x; ic < ICH; ic += 256) {
            float v[9];
#pragma unroll
            for (int t = 0; t < 9; t++) v[t] = sm[ic * 9 + t];
            float s9 = 0.f, va[3] = {0, 0, 0}, vb[3] = {0, 0, 0};
#pragma unroll
            for (int a = 0; a < 3; a++)
#pragma unroll
                for (int bb = 0; bb < 3; bb++) {
                    float x = v[a * 3 + bb];
                    s9 += x; va[a] += x; vb[bb] += x;
                }
            g_Aall[(size_t)oc1 * K1 + ic] = __float2bfloat16(s9);
#pragma unroll
            for (int a = 0; a < 3; a++)
                g_Aall[(size_t)(512 + oc1 * 3 + a) * K1 + ic] = __float2bfloat16(va[a]);
#pragma unroll
            for (int bb = 0; bb < 3; bb++)
                g_Aall[(size_t)(2048 + oc1 * 3 + bb) * K1 + ic] = __float2bfloat16(vb[bb]);
#pragma unroll
            for (int t = 0; t < 9; t++)
                g_Aall[(size_t)(3584 + oc1 * 9 + t) * K1 + ic] = __float2bfloat16(v[t]);
        }
    }
}

// ---------------- fused prep B: w2 cast + img transpose ----------------
#define W2B_BLOCKS 2304
__global__ __launch_bounds__(256) void prepB_k(const float4* __restrict__ w2,
                                               const float* __restrict__ noise,
                                               float* __restrict__ out_img) {
    int bid = blockIdx.x;
    if (bid < W2B_BLOCKS) {
        int i = bid * 256 + threadIdx.x;
        float4 v = w2[i];
        __nv_bfloat162 lo, hi;
        lo.x = __float2bfloat16(v.x); lo.y = __float2bfloat16(v.y);
        hi.x = __float2bfloat16(v.z); hi.y = __float2bfloat16(v.w);
        uint2 o;
        o.x = *(uint32_t*)&lo; o.y = *(uint32_t*)&hi;
        ((uint2*)g_W2b)[i] = o;
    } else {
        __shared__ float tile[32][33];
        int t = bid - W2B_BLOCKS;
        int b = t / (19 * 24);
        int r0 = t % (19 * 24);
        int s0 = (r0 % 19) * 32, c0 = (r0 / 19) * 32;
        int tx = threadIdx.x & 31, ty = threadIdx.x >> 5;
        for (int r = ty; r < 32; r += 8) {
            int s = s0 + tx;
            if (s < 577) tile[r][tx] = noise[(size_t)b * 443136 + (c0 + r) * 577 + s];
        }
        __syncthreads();
        for (int r = ty; r < 32; r += 8) {
            int s = s0 + r;
            if (s < 577) out_img[(size_t)s * (B_ * 768) + b * 768 + c0 + tx] = tile[tx][r];
        }
    }
}

// ---------------- GEMM core: BK=32, 2-stage, frag double-buffer, 3 CTAs/SM ----------------
#define BK      32
#define RSTRIDE 80    // 32 bf16 = 64B + 16B pad; pitch/16 odd -> conflict-free ldmatrix
#define A_ROWS  128
#define B_ROWS  64
#define BUFSZ   ((A_ROWS + B_ROWS) * RSTRIDE)   // 15360 per stage
#define SMEM_SZ (2 * BUFSZ)                     // 30720

template <typename OutT>
__device__ __forceinline__ void gemm_core(
    const __nv_bfloat16* __restrict__ A,   // pre-offset to m0 row + k chunk
    const __nv_bfloat16* __restrict__ B,   // pre-offset to n0 row + k chunk
    OutT* __restrict__ C,                  // pre-offset to (n0,m0)
    int ldk, int ktiles, int ldC, uint32_t sbase)
{
    const int tid = threadIdx.x;
    const int lane = tid & 31, wid = tid >> 5;
    const int wm = wid & 3, wn = wid >> 2;

    float acc[2][4][4];
#pragma unroll
    for (int i = 0; i < 2; i++)
#pragma unroll
        for (int j = 0; j < 4; j++)
#pragma unroll
            for (int q = 0; q < 4; q++) acc[i][j][q] = 0.f;

    // stage = (128 A rows + 64 B rows) x 32 bf16 (64B/row): 768 x 16B chunks, 3/thread
    auto load_tile = [&](int buf, int t) {
        uint32_t s = sbase + buf * BUFSZ;
        int k = t * BK;
#pragma unroll
        for (int i = 0; i < 3; i++) {
            int ch = tid + i * 256;        // 0..767 (A: 0..511, B: 512..767)
            int isB = ch >> 9;
            int row = (ch & 511) >> 2;
            int c4 = ch & 3;
            uint32_t dst = s + isB * (A_ROWS * RSTRIDE) + row * RSTRIDE + c4 * 16;
            const __nv_bfloat16* src =
                (isB ? B + (size_t)row * ldk : A + (size_t)row * ldk) + k + c4 * 8;
            cpasync16(dst, src);
        }
    };

    load_tile(0, 0);
    CP_COMMIT();
    if (ktiles > 1) { load_tile(1, 1); }
    CP_COMMIT();

    const uint32_t rsel = lane & 15;
    const uint32_t chi = (lane >> 4) * 16;

    uint32_t aF[2][2][4];
    uint32_t bF[2][4][2];

    auto ld_frags = [&](int fb, uint32_t sA, uint32_t sB, int ks) {
        uint32_t colB = ks * 32 + chi;
#pragma unroll
        for (int mt = 0; mt < 2; mt++) {
            uint32_t addr = sA + (wm * 32 + mt * 16 + rsel) * RSTRIDE + colB;
            ldsm_x4(aF[fb][mt][0], aF[fb][mt][1], aF[fb][mt][2], aF[fb][mt][3], addr);
        }
#pragma unroll
        for (int p = 0; p < 2; p++) {
            uint32_t r0, r1, r2, r3;
            uint32_t addr = sB + (wn * 32 + p * 16 + rsel) * RSTRIDE + colB;
            ldsm_x4(r0, r1, r2, r3, addr);
            bF[fb][2 * p][0] = r0; bF[fb][2 * p][1] = r2;
            bF[fb][2 * p + 1][0] = r1; bF[fb][2 * p + 1][1] = r3;
        }
    };
    auto do_mma = [&](int fb) {
#pragma unroll
        for (int mt = 0; mt < 2; mt++)
#pragma unroll
            for (int nt = 0; nt < 4; nt++)
                mma_bf16(acc[mt][nt], aF[fb][mt], bF[fb][nt]);
    };

    for (int t = 0; t < ktiles; t++) {
        if (t + 1 < ktiles)
            asm volatile("cp.async.wait_group 1;\n" ::: "memory");
        else
            asm volatile("cp.async.wait_group 0;\n" ::: "memory");
        __syncthreads();

        int buf = t & 1;
        uint32_t sA = sbase + buf * BUFSZ;
        uint32_t sB = sA + A_ROWS * RSTRIDE;

        ld_frags(0, sA, sB, 0);
        ld_frags(1, sA, sB, 1);      // both ks fragments in regs
        do_mma(0);
        __syncthreads();             // smem reads done
        if (t + 2 < ktiles) {
            load_tile(buf, t + 2);
            CP_COMMIT();
        }
        do_mma(1);
    }

    const int mrow = lane >> 2, ncol = (lane & 3) * 2;
#pragma unroll
    for (int mt = 0; mt < 2; mt++)
#pragma unroll
        for (int nt = 0; nt < 4; nt++) {
            int m = wm * 32 + mt * 16 + mrow;
            int n = wn * 32 + nt * 8 + ncol;
            store_c(&C[(size_t)n * ldC + m],           acc[mt][nt][0]);
            store_c(&C[(size_t)(n + 1) * ldC + m],     acc[mt][nt][1]);
            store_c(&C[(size_t)n * ldC + m + 8],       acc[mt][nt][2]);
            store_c(&C[(size_t)(n + 1) * ldC + m + 8], acc[mt][nt][3]);
        }
}

// segmented GEMM1: 4 class-segments in one launch. 292 CTAs (single wave at 3/SM).
__global__ __launch_bounds__(256, 3) void gemm_seg_k() {
    extern __shared__ __align__(128) char smem_raw[];
    uint32_t sbase = smem_u32(smem_raw);
    int bid = blockIdx.x;
    int seg = (bid < 28) ? 0 : (bid < 88) ? 1 : (bid < 148) ? 2 : 3;
    const int segStart[4] = {0, 28, 88, 148};
    const int segMt[4]    = {4, 12, 12, 36};
    const int segArow[4]  = {0, 512, 2048, 3584};
    const int segBrow[4]  = {0, 448, 768, 1088};
    const int segCoff[4]  = {P_II_OFF, P_EI_OFF, P_IE_OFF, P_EE_OFF};
    const int segLd[4]    = {512, 1536, 1536, 4608};
    int local = bid - segStart[seg];
    int bx = local % segMt[seg], by = local / segMt[seg];
    int m0 = bx * 128, n0 = by * 64;
    const __nv_bfloat16* A = g_Aall + (size_t)(segArow[seg] + m0) * K1;
    const __nv_bfloat16* B = g_Bx2 + (size_t)(segBrow[seg] + n0) * K1;
    __nv_bfloat16* C = g_Pcat + segCoff[seg] + (size_t)n0 * segLd[seg] + m0;
    gemm_core<__nv_bfloat16>(A, B, C, K1, K1 / BK, segLd[seg], sbase);
}

// GEMM2 split-K
__global__ __launch_bounds__(256, 3) void gemm2_k() {
    extern __shared__ __align__(128) char smem_raw[];
    uint32_t sbase = smem_u32(smem_raw);
    int m0 = blockIdx.x * 128, n0 = blockIdx.y * 64;
    int z = blockIdx.z;
    int kchunk = K2 / KSPLIT;                 // 384
    const __nv_bfloat16* A = g_W2b + (size_t)m0 * K2 + z * kchunk;
    const __nv_bfloat16* B = g_Tbb + (size_t)n0 * K2 + z * kchunk;
    float* C = g_part + (size_t)z * NPAD * OC2 + (size_t)n0 * OC2 + m0;
    gemm_core<float>(A, B, C, K2, kchunk / BK, OC2, sbase);
}

// ---------------- sparse per-label accumulation (class-aware) -> g_Tbb[bl][k] ----------------
__global__ __launch_bounds__(512) void acc_kernel(const float* __restrict__ b1) {
    const int bl = blockIdx.x;
    const int b = bl / NL;
    const int l = bl % NL;
    const int oc1 = threadIdx.x;

    __shared__ int msh[NPIX];
    for (int i = threadIdx.x; i < NPIX; i += 512) msh[i] = g_m[b * NPIX + i];
    __syncthreads();

    const int lo[3][3] = {{0, 0, 1}, {0, 0, 1}, {3, 4, 5}};
    const int hi[3][3] = {{18, 19, 20}, {22, 23, 23}, {22, 23, 23}};

    float T9[9];
#pragma unroll
    for (int k = 0; k < 9; k++) T9[k] = 0.f;

    for (int pix = 0; pix < NPIX; pix++) {
        if (msh[pix] != l) continue;
        int p = pix / 24, q = pix % 24;
        bool Ip = (p >= 5 && p <= 18), Iq = (q >= 5 && q <= 18);
        int rep = (p < 5) ? p : p - 14;
        int req = (q < 5) ? q : q - 14;

        if (Ip && Iq) {
            int slot = b * 196 + (p - 5) * 14 + (q - 5);
            float s = __bfloat162float(g_Pcat[P_II_OFF + (size_t)slot * 512 + oc1]);
#pragma unroll
            for (int k = 0; k < 9; k++) T9[k] += s;
        } else if (!Ip && Iq) {
            int slot = b * 140 + rep * 14 + (q - 5);
            const __nv_bfloat16* v = &g_Pcat[P_EI_OFF + (size_t)slot * 1536 + oc1 * 3];
            float ra[3];
#pragma unroll
            for (int a = 0; a < 3; a++) ra[a] = __bfloat162float(v[a]);
#pragma unroll
            for (int dr = 0; dr < 3; dr++) {
                float s = 0.f;
#pragma unroll
                for (int a = 0; a < 3; a++)
                    if (p >= lo[dr][a] && p <= hi[dr][a]) s += ra[a];
                T9[dr * 3 + 0] += s; T9[dr * 3 + 1] += s; T9[dr * 3 + 2] += s;
            }
        } else if (Ip) {
            int slot = b * 140 + (p - 5) * 10 + req;
            const __nv_bfloat16* v = &g_Pcat[P_IE_OFF + (size_t)slot * 1536 + oc1 * 3];
            float rb[3];
#pragma unroll
            for (int bb = 0; bb < 3; bb++) rb[bb] = __bfloat162float(v[bb]);
#pragma unroll
            for (int dc = 0; dc < 3; dc++) {
                float s = 0.f;
#pragma unroll
                for (int bb = 0; bb < 3; bb++)
                    if (q >= lo[dc][bb] && q <= hi[dc][bb]) s += rb[bb];
                T9[0 + dc] += s; T9[3 + dc] += s; T9[6 + dc] += s;
            }
        } else {
            int slot = b * 100 + rep * 10 + req;
            const __nv_bfloat16* v = &g_Pcat[P_EE_OFF + (size_t)slot * 4608 + oc1 * 9];
            float vv[9];
#pragma unroll
            for (int t = 0; t < 9; t++) vv[t] = __bfloat162float(v[t]);
            float rs[3][3];
#pragma unroll
            for (int dr = 0; dr < 3; dr++)
#pragma unroll
                for (int bb = 0; bb < 3; bb++) {
                    float s = 0.f;
#pragma unroll
                    for (int a = 0; a < 3; a++)
                        if (p >= lo[dr][a] && p <= hi[dr][a]) s += vv[a * 3 + bb];
                    rs[dr][bb] = s;
                }
#pragma unroll
            for (int dr = 0; dr < 3; dr++)
#pragma unroll
                for (int dc = 0; dc < 3; dc++) {
                    float s = 0.f;
#pragma unroll
                    for (int bb = 0; bb < 3; bb++)
                        if (q >= lo[dc][bb] && q <= hi[dc][bb]) s += rs[dr][bb];
                    T9[dr * 3 + dc] += s;
                }
        }
    }

    const float nrc[3] = {20.f, 24.f, 20.f};
    float bb1 = b1[oc1];
#pragma unroll
    for (int k = 0; k < 9; k++) {
        float t = (T9[k] + nrc[k / 3] * nrc[k % 3] * bb1) * (1.0f / 576.0f);
        g_Tbb[(size_t)bl * K2 + oc1 * 9 + k] = __float2bfloat16(t);
    }
}

// ---------------- fused reduce + expand (float4 stores) ----------------
// block = (b,l); phase 1: 512 threads reduce split-K into smem;
// phase 2: thread (grp, c4) writes float4 for o = grp, grp+4, ...
__global__ __launch_bounds__(512) void expand2_k(const float* __restrict__ w3,
                                                 const float* __restrict__ b3,
                                                 const float* __restrict__ b2,
                                                 float4* __restrict__ out) {
    __shared__ float ssum[512];
    int bl = blockIdx.x;
    int b = bl / NL, l = bl % NL;
    int c = threadIdx.x;
    const int S = NPAD * OC2;
    float s = b2[c];
#pragma unroll
    for (int z = 0; z < KSPLIT; z++) s += g_part[(size_t)z * S + bl * OC2 + c];
    ssum[c] = s;
    __syncthreads();

    int c4 = threadIdx.x & 127;
    int grp = threadIdx.x >> 7;
    float4 sv = *(const float4*)&ssum[c4 * 4];
    size_t base4 = (((size_t)b * 77 * NL + l) * 512) / 4 + c4;   // float4 index
    for (int o = grp; o < 77; o += 4) {
        float w = __ldg(&w3[o]), bb = __ldg(&b3[o]);
        float4 r = make_float4(w * sv.x + bb, w * sv.y + bb, w * sv.z + bb, w * sv.w + bb);
        __stcs(&out[base4 + (size_t)o * NL * 128], r);
    }
}

// ---------------- launch ----------------
extern "C" void kernel_launch(void* const* d_in, const int* in_sizes, int n_in,
                              void* d_out, int out_size) {
    const float* noise   = (const float*)d_in[0];
    const int*   targets = (const int*)  d_in[1];
    const float* w1      = (const float*)d_in[2];
    const float* b1      = (const float*)d_in[3];
    const float* w2      = (const float*)d_in[4];
    const float* b2      = (const float*)d_in[5];
    const float* w3      = (const float*)d_in[6];
    const float* b3      = (const float*)d_in[7];
    float* out      = (float*)d_out;
    float* out_img  = out;
    float* out_text = out + IMG_ELEMS;

    cudaFuncSetAttribute(gemm_seg_k, cudaFuncAttributeMaxDynamicSharedMemorySize, SMEM_SZ);
    cudaFuncSetAttribute(gemm2_k,    cudaFuncAttributeMaxDynamicSharedMemorySize, SMEM_SZ);

    prepA_k<<<XPACK_BLOCKS + 512, 256>>>(noise, w1);                       // 1
    prepB_k<<<W2B_BLOCKS + 912, 256>>>((const float4*)w2, noise, out_img); // 2
    labels_k<<<(B_ * NPIX + 255) / 256, 256>>>(targets);                   // 3

    gemm_seg_k<<<292, 256, SMEM_SZ>>>();                                   // 4 (profiled)
    acc_kernel<<<NBL, 512>>>(b1);                                          // 5
    gemm2_k<<<dim3(OC2 / 128, NPAD / 64, KSPLIT), 256, SMEM_SZ>>>();       // 6
    expand2_k<<<NBL, 512>>>(w3, b3, b2, (float4*)out_text);                // 7
}

// round 11
// speedup vs baseline: 1.0200x; 1.0200x over previous
#include <cuda_runtime.h>
#include <cuda_bf16.h>
#include <cstdint>

// ---------------- problem constants ----------------
#define B_      2
#define NPIX    576
#define NL      171
#define NBL     342
#define NPAD    384
#define ICH     768
#define OC1     512
#define OC2     512
#define K1      768
#define K2      4608
#define KSPLIT  12
#define IMG_ELEMS  (577*B_*768)
#define TXT_ELEMS  (B_*77*NL*512)

// pixel classes: interior rows/cols = [5,18] (14), edge = 10
#define BX_ROWS 1344
#define AROWS   8192
#define P_II_OFF 0
#define P_EI_OFF 229376
#define P_IE_OFF 720896
#define P_EE_OFF 1212416
#define P_TOTAL  2392064

// ---------------- scratch ----------------
__device__ __align__(128) __nv_bfloat16 g_Aall[(size_t)AROWS * K1];
__device__ __align__(128) __nv_bfloat16 g_Bx2[(size_t)BX_ROWS * K1];
__device__ __align__(128) __nv_bfloat16 g_Pcat[P_TOTAL];
__device__ __align__(128) __nv_bfloat16 g_W2b[OC2 * K2];
__device__ __align__(128) __nv_bfloat16 g_Tbb[NPAD * K2];
__device__ __align__(128) float         g_part[KSPLIT * NPAD * OC2];
__device__ int g_m[B_ * NPIX];

// ---------------- PTX helpers ----------------
__device__ __forceinline__ uint32_t smem_u32(const void* p) {
    uint32_t a;
    asm("{ .reg .u64 t; cvta.to.shared.u64 t, %1; cvt.u32.u64 %0, t; }" : "=r"(a) : "l"(p));
    return a;
}
__device__ __forceinline__ void cpasync16(uint32_t dst, const void* src) {
    asm volatile("cp.async.cg.shared.global [%0], [%1], 16;\n" :: "r"(dst), "l"(src));
}
#define CP_COMMIT() asm volatile("cp.async.commit_group;\n" ::: "memory")

__device__ __forceinline__ void ldsm_x4(uint32_t& r0, uint32_t& r1, uint32_t& r2,
                                        uint32_t& r3, uint32_t addr) {
    asm volatile("ldmatrix.sync.aligned.m8n8.x4.shared.b16 {%0,%1,%2,%3}, [%4];"
                 : "=r"(r0), "=r"(r1), "=r"(r2), "=r"(r3) : "r"(addr));
}
__device__ __forceinline__ void mma_bf16(float* c, const uint32_t* a, const uint32_t* b) {
    asm volatile("mma.sync.aligned.m16n8k16.row.col.f32.bf16.bf16.f32 "
                 "{%0,%1,%2,%3}, {%4,%5,%6,%7}, {%8,%9}, {%0,%1,%2,%3};"
                 : "+f"(c[0]), "+f"(c[1]), "+f"(c[2]), "+f"(c[3])
                 : "r"(a[0]), "r"(a[1]), "r"(a[2]), "r"(a[3]), "r"(b[0]), "r"(b[1]));
}
__device__ __forceinline__ void store_c(float* p, float v) { *p = v; }
__device__ __forceinline__ void store_c(__nv_bfloat16* p, float v) { *p = __float2bfloat16(v); }

// pixel -> B-matrix row (class-sorted layout)
__device__ __forceinline__ int browmap(int b, int pix) {
    int p = pix / 24, q = pix % 24;
    bool Ip = (p >= 5 && p <= 18), Iq = (q >= 5 && q <= 18);
    int rep = (p < 5) ? p : p - 14;
    int req = (q < 5) ? q : q - 14;
    if (Ip && Iq)  return        b * 196 + (p - 5) * 14 + (q - 5);
    if (!Ip && Iq) return 448 +  b * 140 + rep * 14 + (q - 5);
    if (Ip)        return 768 +  b * 140 + (p - 5) * 10 + req;
    return 1088 + b * 100 + rep * 10 + req;
}

// ---------------- labels ----------------
__global__ void labels_k(const int* __restrict__ targets) {
    int i = blockIdx.x * blockDim.x + threadIdx.x;
    if (i >= B_ * NPIX) return;
    int b = i / NPIX, pix = i % NPIX;
    int pi = pix / 24, qj = pix % 24;
    g_m[i] = targets[b * 147456 + (pi * 16) * 384 + qj * 16];
}

// ---------------- fused prep A: xpack (864 blocks) + weight build (512 blocks) ----------------
#define XPACK_BLOCKS (18 * 24 * 2)
__global__ __launch_bounds__(256) void prepA_k(const float* __restrict__ noise,
                                               const float* __restrict__ w1) {
    int bid = blockIdx.x;
    if (bid < XPACK_BLOCKS) {
        __shared__ float tile[32][33];
        int b = bid / (18 * 24);
        int r0 = bid % (18 * 24);
        int p0 = (r0 % 18) * 32, c0 = (r0 / 18) * 32;
        int tx = threadIdx.x & 31, ty = threadIdx.x >> 5;
        for (int r = ty; r < 32; r += 8)
            tile[r][tx] = noise[(size_t)b * 443136 + (c0 + r) * 577 + 1 + p0 + tx];
        __syncthreads();
        for (int r = ty; r < 32; r += 8) {
            int dstrow = browmap(b, p0 + r);
            g_Bx2[(size_t)dstrow * K1 + c0 + tx] = __float2bfloat16(tile[tx][r]);
        }
    } else {
        __shared__ float sm[ICH * 9];
        int oc1 = bid - XPACK_BLOCKS;
        const float4* src = (const float4*)(w1 + (size_t)oc1 * ICH * 9);
        for (int i = threadIdx.x; i < ICH * 9 / 4; i += 256)
            ((float4*)sm)[i] = src[i];
        __syncthreads();
        for (int ic = threadIdx.x; ic < ICH; ic += 256) {
            float v[9];
#pragma unroll
            for (int t = 0; t < 9; t++) v[t] = sm[ic * 9 + t];
            float s9 = 0.f, va[3] = {0, 0, 0}, vb[3] = {0, 0, 0};
#pragma unroll
            for (int a = 0; a < 3; a++)
#pragma unroll
                for (int bb = 0; bb < 3; bb++) {
                    float x = v[a * 3 + bb];
                    s9 += x; va[a] += x; vb[bb] += x;
                }
            g_Aall[(size_t)oc1 * K1 + ic] = __float2bfloat16(s9);
#pragma unroll
            for (int a = 0; a < 3; a++)
                g_Aall[(size_t)(512 + oc1 * 3 + a) * K1 + ic] = __float2bfloat16(va[a]);
#pragma unroll
            for (int bb = 0; bb < 3; bb++)
                g_Aall[(size_t)(2048 + oc1 * 3 + bb) * K1 + ic] = __float2bfloat16(vb[bb]);
#pragma unroll
            for (int t = 0; t < 9; t++)
                g_Aall[(size_t)(3584 + oc1 * 9 + t) * K1 + ic] = __float2bfloat16(v[t]);
        }
    }
}

// ---------------- fused prep B: w2 cast + img transpose ----------------
#define W2B_BLOCKS 2304
__global__ __launch_bounds__(256) void prepB_k(const float4* __restrict__ w2,
                                               const float* __restrict__ noise,
                                               float* __restrict__ out_img) {
    int bid = blockIdx.x;
    if (bid < W2B_BLOCKS) {
        int i = bid * 256 + threadIdx.x;
        float4 v = w2[i];
        __nv_bfloat162 lo, hi;
        lo.x = __float2bfloat16(v.x); lo.y = __float2bfloat16(v.y);
        hi.x = __float2bfloat16(v.z); hi.y = __float2bfloat16(v.w);
        uint2 o;
        o.x = *(uint32_t*)&lo; o.y = *(uint32_t*)&hi;
        ((uint2*)g_W2b)[i] = o;
    } else {
        __shared__ float tile[32][33];
        int t = bid - W2B_BLOCKS;
        int b = t / (19 * 24);
        int r0 = t % (19 * 24);
        int s0 = (r0 % 19) * 32, c0 = (r0 / 19) * 32;
        int tx = threadIdx.x & 31, ty = threadIdx.x >> 5;
        for (int r = ty; r < 32; r += 8) {
            int s = s0 + tx;
            if (s < 577) tile[r][tx] = noise[(size_t)b * 443136 + (c0 + r) * 577 + s];
        }
        __syncthreads();
        for (int r = ty; r < 32; r += 8) {
            int s = s0 + r;
            if (s < 577) out_img[(size_t)s * (B_ * 768) + b * 768 + c0 + tx] = tile[tx][r];
        }
    }
}

// ---------------- GEMM core (round-9 best: BK=64, 2-stage, frag double-buffer) ----------------
#define RSTRIDE 144
#define A_ROWS  128
#define B_ROWS  64
#define BUFSZ   ((A_ROWS + B_ROWS) * RSTRIDE)   // 27648
#define SMEM_SZ (2 * BUFSZ)                     // 55296

template <typename OutT>
__device__ __forceinline__ void gemm_core(
    const __nv_bfloat16* __restrict__ A,   // pre-offset to m0 row + k chunk
    const __nv_bfloat16* __restrict__ B,   // pre-offset to n0 row + k chunk
    OutT* __restrict__ C,                  // pre-offset to (n0,m0)
    int ldk, int ktiles, int ldC, uint32_t sbase)
{
    const int tid = threadIdx.x;
    const int lane = tid & 31, wid = tid >> 5;
    const int wm = wid & 3, wn = wid >> 2;

    float acc[2][4][4];
#pragma unroll
    for (int i = 0; i < 2; i++)
#pragma unroll
        for (int j = 0; j < 4; j++)
#pragma unroll
            for (int q = 0; q < 4; q++) acc[i][j][q] = 0.f;

    auto load_tile = [&](int buf, int t) {
        uint32_t s = sbase + buf * BUFSZ;
        int k = t * 64;
#pragma unroll
        for (int i = 0; i < 6; i++) {
            int ch = tid + i * 256;
            int isB = ch >> 10;
            int row = (ch >> 3) & (isB ? 63 : 127);
            int c8 = ch & 7;
            uint32_t dst = s + isB * (A_ROWS * RSTRIDE) + row * RSTRIDE + c8 * 16;
            const __nv_bfloat16* src =
                (isB ? B + (size_t)row * ldk : A + (size_t)row * ldk) + k + c8 * 8;
            cpasync16(dst, src);
        }
    };

    load_tile(0, 0);
    CP_COMMIT();
    if (ktiles > 1) { load_tile(1, 1); }
    CP_COMMIT();

    const uint32_t rsel = lane & 15;
    const uint32_t chi = (lane >> 4) * 16;

    uint32_t aF[2][2][4];
    uint32_t bF[2][4][2];

    auto ld_frags = [&](int fb, uint32_t sA, uint32_t sB, int ks) {
        uint32_t colB = ks * 32 + chi;
#pragma unroll
        for (int mt = 0; mt < 2; mt++) {
            uint32_t addr = sA + (wm * 32 + mt * 16 + rsel) * RSTRIDE + colB;
            ldsm_x4(aF[fb][mt][0], aF[fb][mt][1], aF[fb][mt][2], aF[fb][mt][3], addr);
        }
#pragma unroll
        for (int p = 0; p < 2; p++) {
            uint32_t r0, r1, r2, r3;
            uint32_t addr = sB + (wn * 32 + p * 16 + rsel) * RSTRIDE + colB;
            ldsm_x4(r0, r1, r2, r3, addr);
            bF[fb][2 * p][0] = r0; bF[fb][2 * p][1] = r2;
            bF[fb][2 * p + 1][0] = r1; bF[fb][2 * p + 1][1] = r3;
        }
    };
    auto do_mma = [&](int fb) {
#pragma unroll
        for (int mt = 0; mt < 2; mt++)
#pragma unroll
            for (int nt = 0; nt < 4; nt++)
                mma_bf16(acc[mt][nt], aF[fb][mt], bF[fb][nt]);
    };

    for (int t = 0; t < ktiles; t++) {
        if (t + 1 < ktiles)
            asm volatile("cp.async.wait_group 1;\n" ::: "memory");
        else
            asm volatile("cp.async.wait_group 0;\n" ::: "memory");
        __syncthreads();

        int buf = t & 1;
        uint32_t sA = sbase + buf * BUFSZ;
        uint32_t sB = sA + A_ROWS * RSTRIDE;

        ld_frags(0, sA, sB, 0);
        ld_frags(1, sA, sB, 1);
        do_mma(0);
        ld_frags(0, sA, sB, 2);
        do_mma(1);
        ld_frags(1, sA, sB, 3);
        do_mma(0);
        __syncthreads();
        if (t + 2 < ktiles) {
            load_tile(buf, t + 2);
            CP_COMMIT();
        }
        do_mma(1);
    }

    const int mrow = lane >> 2, ncol = (lane & 3) * 2;
#pragma unroll
    for (int mt = 0; mt < 2; mt++)
#pragma unroll
        for (int nt = 0; nt < 4; nt++) {
            int m = wm * 32 + mt * 16 + mrow;
            int n = wn * 32 + nt * 8 + ncol;
            store_c(&C[(size_t)n * ldC + m],           acc[mt][nt][0]);
            store_c(&C[(size_t)(n + 1) * ldC + m],     acc[mt][nt][1]);
            store_c(&C[(size_t)n * ldC + m + 8],       acc[mt][nt][2]);
            store_c(&C[(size_t)(n + 1) * ldC + m + 8], acc[mt][nt][3]);
        }
}

// segmented GEMM1: 4 class-segments in one launch. 292 CTAs.
__global__ __launch_bounds__(256) void gemm_seg_k() {
    extern __shared__ __align__(128) char smem_raw[];
    uint32_t sbase = smem_u32(smem_raw);
    int bid = blockIdx.x;
    int seg = (bid < 28) ? 0 : (bid < 88) ? 1 : (bid < 148) ? 2 : 3;
    const int segStart[4] = {0, 28, 88, 148};
    const int segMt[4]    = {4, 12, 12, 36};
    const int segArow[4]  = {0, 512, 2048, 3584};
    const int segBrow[4]  = {0, 448, 768, 1088};
    const int segCoff[4]  = {P_II_OFF, P_EI_OFF, P_IE_OFF, P_EE_OFF};
    const int segLd[4]    = {512, 1536, 1536, 4608};
    int local = bid - segStart[seg];
    int bx = local % segMt[seg], by = local / segMt[seg];
    int m0 = bx * 128, n0 = by * 64;
    const __nv_bfloat16* A = g_Aall + (size_t)(segArow[seg] + m0) * K1;
    const __nv_bfloat16* B = g_Bx2 + (size_t)(segBrow[seg] + n0) * K1;
    __nv_bfloat16* C = g_Pcat + segCoff[seg] + (size_t)n0 * segLd[seg] + m0;
    gemm_core<__nv_bfloat16>(A, B, C, K1, K1 / 64, segLd[seg], sbase);
}

// GEMM2 split-K
__global__ __launch_bounds__(256) void gemm2_k() {
    extern __shared__ __align__(128) char smem_raw[];
    uint32_t sbase = smem_u32(smem_raw);
    int m0 = blockIdx.x * 128, n0 = blockIdx.y * 64;
    int z = blockIdx.z;
    int kt = K2 / KSPLIT / 64;   // 6
    const __nv_bfloat16* A = g_W2b + (size_t)m0 * K2 + z * kt * 64;
    const __nv_bfloat16* B = g_Tbb + (size_t)n0 * K2 + z * kt * 64;
    float* C = g_part + (size_t)z * NPAD * OC2 + (size_t)n0 * OC2 + m0;
    gemm_core<float>(A, B, C, K2, kt, OC2, sbase);
}

// ---------------- sparse per-label accumulation (class-aware) -> g_Tbb[bl][k] ----------------
__global__ __launch_bounds__(512) void acc_kernel(const float* __restrict__ b1) {
    const int bl = blockIdx.x;
    const int b = bl / NL;
    const int l = bl % NL;
    const int oc1 = threadIdx.x;

    __shared__ int msh[NPIX];
    for (int i = threadIdx.x; i < NPIX; i += 512) msh[i] = g_m[b * NPIX + i];
    __syncthreads();

    const int lo[3][3] = {{0, 0, 1}, {0, 0, 1}, {3, 4, 5}};
    const int hi[3][3] = {{18, 19, 20}, {22, 23, 23}, {22, 23, 23}};

    float T9[9];
#pragma unroll
    for (int k = 0; k < 9; k++) T9[k] = 0.f;

    for (int pix = 0; pix < NPIX; pix++) {
        if (msh[pix] != l) continue;
        int p = pix / 24, q = pix % 24;
        bool Ip = (p >= 5 && p <= 18), Iq = (q >= 5 && q <= 18);
        int rep = (p < 5) ? p : p - 14;
        int req = (q < 5) ? q : q - 14;

        if (Ip && Iq) {
            int slot = b * 196 + (p - 5) * 14 + (q - 5);
            float s = __bfloat162float(g_Pcat[P_II_OFF + (size_t)slot * 512 + oc1]);
#pragma unroll
            for (int k = 0; k < 9; k++) T9[k] += s;
        } else if (!Ip && Iq) {
            int slot = b * 140 + rep * 14 + (q - 5);
            const __nv_bfloat16* v = &g_Pcat[P_EI_OFF + (size_t)slot * 1536 + oc1 * 3];
            float ra[3];
#pragma unroll
            for (int a = 0; a < 3; a++) ra[a] = __bfloat162float(v[a]);
#pragma unroll
            for (int dr = 0; dr < 3; dr++) {
                float s = 0.f;
#pragma unroll
                for (int a = 0; a < 3; a++)
                    if (p >= lo[dr][a] && p <= hi[dr][a]) s += ra[a];
                T9[dr * 3 + 0] += s; T9[dr * 3 + 1] += s; T9[dr * 3 + 2] += s;
            }
        } else if (Ip) {
            int slot = b * 140 + (p - 5) * 10 + req;
            const __nv_bfloat16* v = &g_Pcat[P_IE_OFF + (size_t)slot * 1536 + oc1 * 3];
            float rb[3];
#pragma unroll
            for (int bb = 0; bb < 3; bb++) rb[bb] = __bfloat162float(v[bb]);
#pragma unroll
            for (int dc = 0; dc < 3; dc++) {
                float s = 0.f;
#pragma unroll
                for (int bb = 0; bb < 3; bb++)
                    if (q >= lo[dc][bb] && q <= hi[dc][bb]) s += rb[bb];
                T9[0 + dc] += s; T9[3 + dc] += s; T9[6 + dc] += s;
            }
        } else {
            int slot = b * 100 + rep * 10 + req;
            const __nv_bfloat16* v = &g_Pcat[P_EE_OFF + (size_t)slot * 4608 + oc1 * 9];
            float vv[9];
#pragma unroll
            for (int t = 0; t < 9; t++) vv[t] = __bfloat162float(v[t]);
            float rs[3][3];
#pragma unroll
            for (int dr = 0; dr < 3; dr++)
#pragma unroll
                for (int bb = 0; bb < 3; bb++) {
                    float s = 0.f;
#pragma unroll
                    for (int a = 0; a < 3; a++)
                        if (p >= lo[dr][a] && p <= hi[dr][a]) s += vv[a * 3 + bb];
                    rs[dr][bb] = s;
                }
#pragma unroll
            for (int dr = 0; dr < 3; dr++)
#pragma unroll
                for (int dc = 0; dc < 3; dc++) {
                    float s = 0.f;
#pragma unroll
                    for (int bb = 0; bb < 3; bb++)
                        if (q >= lo[dc][bb] && q <= hi[dc][bb]) s += rs[dr][bb];
                    T9[dr * 3 + dc] += s;
                }
        }
    }

    const float nrc[3] = {20.f, 24.f, 20.f};
    float bb1 = b1[oc1];
#pragma unroll
    for (int k = 0; k < 9; k++) {
        float t = (T9[k] + nrc[k / 3] * nrc[k % 3] * bb1) * (1.0f / 576.0f);
        g_Tbb[(size_t)bl * K2 + oc1 * 9 + k] = __float2bfloat16(t);
    }
}

// ---------------- fused reduce + expand (float4 stores) ----------------
__global__ __launch_bounds__(512) void expand2_k(const float* __restrict__ w3,
                                                 const float* __restrict__ b3,
                                                 const float* __restrict__ b2,
                                                 float4* __restrict__ out) {
    __shared__ float ssum[512];
    int bl = blockIdx.x;
    int b = bl / NL, l = bl % NL;
    int c = threadIdx.x;
    const int S = NPAD * OC2;
    float s = b2[c];
#pragma unroll
    for (int z = 0; z < KSPLIT; z++) s += g_part[(size_t)z * S + bl * OC2 + c];
    ssum[c] = s;
    __syncthreads();

    int c4 = threadIdx.x & 127;
    int grp = threadIdx.x >> 7;
    float4 sv = *(const float4*)&ssum[c4 * 4];
    size_t base4 = (((size_t)b * 77 * NL + l) * 512) / 4 + c4;   // float4 index
    for (int o = grp; o < 77; o += 4) {
        float w = __ldg(&w3[o]), bb = __ldg(&b3[o]);
        float4 r = make_float4(w * sv.x + bb, w * sv.y + bb, w * sv.z + bb, w * sv.w + bb);
        __stcs(&out[base4 + (size_t)o * NL * 128], r);
    }
}

// ---------------- launch ----------------
extern "C" void kernel_launch(void* const* d_in, const int* in_sizes, int n_in,
                              void* d_out, int out_size) {
    const float* noise   = (const float*)d_in[0];
    const int*   targets = (const int*)  d_in[1];
    const float* w1      = (const float*)d_in[2];
    const float* b1      = (const float*)d_in[3];
    const float* w2      = (const float*)d_in[4];
    const float* b2      = (const float*)d_in[5];
    const float* w3      = (const float*)d_in[6];
    const float* b3      = (const float*)d_in[7];
    float* out      = (float*)d_out;
    float* out_img  = out;
    float* out_text = out + IMG_ELEMS;

    cudaFuncSetAttribute(gemm_seg_k, cudaFuncAttributeMaxDynamicSharedMemorySize, SMEM_SZ);
    cudaFuncSetAttribute(gemm2_k,    cudaFuncAttributeMaxDynamicSharedMemorySize, SMEM_SZ);

    // order: 4th launch (ncu -s 5 target) = acc_kernel this round.
    labels_k<<<(B_ * NPIX + 255) / 256, 256>>>(targets);                   // 1
    prepA_k<<<XPACK_BLOCKS + 512, 256>>>(noise, w1);                       // 2
    gemm_seg_k<<<292, 256, SMEM_SZ>>>();                                   // 3
    acc_kernel<<<NBL, 512>>>(b1);                                          // 4 (profiled)
    prepB_k<<<W2B_BLOCKS + 912, 256>>>((const float4*)w2, noise, out_img); // 5
    gemm2_k<<<dim3(OC2 / 128, NPAD / 64, KSPLIT), 256, SMEM_SZ>>>();       // 6
    expand2_k<<<NBL, 512>>>(w3, b3, b2, (float4*)out_text);                // 7
}

// round 12
// speedup vs baseline: 1.5086x; 1.4790x over previous
#include <cuda_runtime.h>
#include <cuda_bf16.h>
#include <cstdint>

// ---------------- problem constants ----------------
#define B_      2
#define NPIX    576
#define NL      171
#define NBL     342
#define NPAD    384
#define ICH     768
#define OC1     512
#define OC2     512
#define K1      768
#define K2      4608
#define KSPLIT  12
#define IMG_ELEMS  (577*B_*768)
#define TXT_ELEMS  (B_*77*NL*512)

// pixel classes: interior rows/cols = [5,18] (14), edge = 10
#define BX_ROWS 1344
#define AROWS   8192
#define P_II_OFF 0
#define P_EI_OFF 229376
#define P_IE_OFF 720896
#define P_EE_OFF 1212416
#define P_TOTAL  2392064

// ---------------- scratch ----------------
__device__ __align__(128) __nv_bfloat16 g_Aall[(size_t)AROWS * K1];
__device__ __align__(128) __nv_bfloat16 g_Bx2[(size_t)BX_ROWS * K1];
__device__ __align__(128) __nv_bfloat16 g_Pcat[P_TOTAL];
__device__ __align__(128) __nv_bfloat16 g_W2b[OC2 * K2];
__device__ __align__(128) __nv_bfloat16 g_Tbb[NPAD * K2];
__device__ __align__(128) float         g_part[KSPLIT * NPAD * OC2];
__device__ unsigned short g_plist[NBL * NPIX];   // per-(b,l) pixel list (ascending)
__device__ int            g_cnt[NBL];

// ---------------- PTX helpers ----------------
__device__ __forceinline__ uint32_t smem_u32(const void* p) {
    uint32_t a;
    asm("{ .reg .u64 t; cvta.to.shared.u64 t, %1; cvt.u32.u64 %0, t; }" : "=r"(a) : "l"(p));
    return a;
}
__device__ __forceinline__ void cpasync16(uint32_t dst, const void* src) {
    asm volatile("cp.async.cg.shared.global [%0], [%1], 16;\n" :: "r"(dst), "l"(src));
}
#define CP_COMMIT() asm volatile("cp.async.commit_group;\n" ::: "memory")

__device__ __forceinline__ void ldsm_x4(uint32_t& r0, uint32_t& r1, uint32_t& r2,
                                        uint32_t& r3, uint32_t addr) {
    asm volatile("ldmatrix.sync.aligned.m8n8.x4.shared.b16 {%0,%1,%2,%3}, [%4];"
                 : "=r"(r0), "=r"(r1), "=r"(r2), "=r"(r3) : "r"(addr));
}
__device__ __forceinline__ void mma_bf16(float* c, const uint32_t* a, const uint32_t* b) {
    asm volatile("mma.sync.aligned.m16n8k16.row.col.f32.bf16.bf16.f32 "
                 "{%0,%1,%2,%3}, {%4,%5,%6,%7}, {%8,%9}, {%0,%1,%2,%3};"
                 : "+f"(c[0]), "+f"(c[1]), "+f"(c[2]), "+f"(c[3])
                 : "r"(a[0]), "r"(a[1]), "r"(a[2]), "r"(a[3]), "r"(b[0]), "r"(b[1]));
}
__device__ __forceinline__ void store_c(float* p, float v) { *p = v; }
__device__ __forceinline__ void store_c(__nv_bfloat16* p, float v) { *p = __float2bfloat16(v); }

// pixel -> B-matrix row (class-sorted layout)
__device__ __forceinline__ int browmap(int b, int pix) {
    int p = pix / 24, q = pix % 24;
    bool Ip = (p >= 5 && p <= 18), Iq = (q >= 5 && q <= 18);
    int rep = (p < 5) ? p : p - 14;
    int req = (q < 5) ? q : q - 14;
    if (Ip && Iq)  return        b * 196 + (p - 5) * 14 + (q - 5);
    if (!Ip && Iq) return 448 +  b * 140 + rep * 14 + (q - 5);
    if (Ip)        return 768 +  b * 140 + (p - 5) * 10 + req;
    return 1088 + b * 100 + rep * 10 + req;
}

// ---------------- labels + per-label pixel lists (deterministic, ascending pix) ----------------
__global__ __launch_bounds__(NPIX) void plist_k(const int* __restrict__ targets) {
    __shared__ int msh[NPIX];
    int b = blockIdx.x;
    int pix = threadIdx.x;
    int pi = pix / 24, qj = pix % 24;
    msh[pix] = targets[b * 147456 + (pi * 16) * 384 + qj * 16];
    __syncthreads();
    int l = threadIdx.x;
    if (l < NL) {
        int base = (b * NL + l) * NPIX;
        int cnt = 0;
        for (int p = 0; p < NPIX; p++)
            if (msh[p] == l) g_plist[base + cnt++] = (unsigned short)p;
        g_cnt[b * NL + l] = cnt;
    }
}

// ---------------- fused prep A: xpack (864 blocks) + weight build (512 blocks) ----------------
#define XPACK_BLOCKS (18 * 24 * 2)
__global__ __launch_bounds__(256) void prepA_k(const float* __restrict__ noise,
                                               const float* __restrict__ w1) {
    int bid = blockIdx.x;
    if (bid < XPACK_BLOCKS) {
        __shared__ float tile[32][33];
        int b = bid / (18 * 24);
        int r0 = bid % (18 * 24);
        int p0 = (r0 % 18) * 32, c0 = (r0 / 18) * 32;
        int tx = threadIdx.x & 31, ty = threadIdx.x >> 5;
        for (int r = ty; r < 32; r += 8)
            tile[r][tx] = noise[(size_t)b * 443136 + (c0 + r) * 577 + 1 + p0 + tx];
        __syncthreads();
        for (int r = ty; r < 32; r += 8) {
            int dstrow = browmap(b, p0 + r);
            g_Bx2[(size_t)dstrow * K1 + c0 + tx] = __float2bfloat16(tile[tx][r]);
        }
    } else {
        __shared__ float sm[ICH * 9];
        int oc1 = bid - XPACK_BLOCKS;
        const float4* src = (const float4*)(w1 + (size_t)oc1 * ICH * 9);
        for (int i = threadIdx.x; i < ICH * 9 / 4; i += 256)
            ((float4*)sm)[i] = src[i];
        __syncthreads();
        for (int ic = threadIdx.x; ic < ICH; ic += 256) {
            float v[9];
#pragma unroll
            for (int t = 0; t < 9; t++) v[t] = sm[ic * 9 + t];
            float s9 = 0.f, va[3] = {0, 0, 0}, vb[3] = {0, 0, 0};
#pragma unroll
            for (int a = 0; a < 3; a++)
#pragma unroll
                for (int bb = 0; bb < 3; bb++) {
                    float x = v[a * 3 + bb];
                    s9 += x; va[a] += x; vb[bb] += x;
                }
            g_Aall[(size_t)oc1 * K1 + ic] = __float2bfloat16(s9);
#pragma unroll
            for (int a = 0; a < 3; a++)
                g_Aall[(size_t)(512 + oc1 * 3 + a) * K1 + ic] = __float2bfloat16(va[a]);
#pragma unroll
            for (int bb = 0; bb < 3; bb++)
                g_Aall[(size_t)(2048 + oc1 * 3 + bb) * K1 + ic] = __float2bfloat16(vb[bb]);
#pragma unroll
            for (int t = 0; t < 9; t++)
                g_Aall[(size_t)(3584 + oc1 * 9 + t) * K1 + ic] = __float2bfloat16(v[t]);
        }
    }
}

// ---------------- fused prep B: w2 cast + img transpose ----------------
#define W2B_BLOCKS 2304
__global__ __launch_bounds__(256) void prepB_k(const float4* __restrict__ w2,
                                               const float* __restrict__ noise,
                                               float* __restrict__ out_img) {
    int bid = blockIdx.x;
    if (bid < W2B_BLOCKS) {
        int i = bid * 256 + threadIdx.x;
        float4 v = w2[i];
        __nv_bfloat162 lo, hi;
        lo.x = __float2bfloat16(v.x); lo.y = __float2bfloat16(v.y);
        hi.x = __float2bfloat16(v.z); hi.y = __float2bfloat16(v.w);
        uint2 o;
        o.x = *(uint32_t*)&lo; o.y = *(uint32_t*)&hi;
        ((uint2*)g_W2b)[i] = o;
    } else {
        __shared__ float tile[32][33];
        int t = bid - W2B_BLOCKS;
        int b = t / (19 * 24);
        int r0 = t % (19 * 24);
        int s0 = (r0 % 19) * 32, c0 = (r0 / 19) * 32;
        int tx = threadIdx.x & 31, ty = threadIdx.x >> 5;
        for (int r = ty; r < 32; r += 8) {
            int s = s0 + tx;
            if (s < 577) tile[r][tx] = noise[(size_t)b * 443136 + (c0 + r) * 577 + s];
        }
        __syncthreads();
        for (int r = ty; r < 32; r += 8) {
            int s = s0 + r;
            if (s < 577) out_img[(size_t)s * (B_ * 768) + b * 768 + c0 + tx] = tile[tx][r];
        }
    }
}

// ---------------- GEMM core (BK=64, 2-stage, frag double-buffer) ----------------
#define RSTRIDE 144
#define A_ROWS  128
#define B_ROWS  64
#define BUFSZ   ((A_ROWS + B_ROWS) * RSTRIDE)   // 27648
#define SMEM_SZ (2 * BUFSZ)                     // 55296

template <typename OutT>
__device__ __forceinline__ void gemm_core(
    const __nv_bfloat16* __restrict__ A,
    const __nv_bfloat16* __restrict__ B,
    OutT* __restrict__ C,
    int ldk, int ktiles, int ldC, uint32_t sbase)
{
    const int tid = threadIdx.x;
    const int lane = tid & 31, wid = tid >> 5;
    const int wm = wid & 3, wn = wid >> 2;

    float acc[2][4][4];
#pragma unroll
    for (int i = 0; i < 2; i++)
#pragma unroll
        for (int j = 0; j < 4; j++)
#pragma unroll
            for (int q = 0; q < 4; q++) acc[i][j][q] = 0.f;

    auto load_tile = [&](int buf, int t) {
        uint32_t s = sbase + buf * BUFSZ;
        int k = t * 64;
#pragma unroll
        for (int i = 0; i < 6; i++) {
            int ch = tid + i * 256;
            int isB = ch >> 10;
            int row = (ch >> 3) & (isB ? 63 : 127);
            int c8 = ch & 7;
            uint32_t dst = s + isB * (A_ROWS * RSTRIDE) + row * RSTRIDE + c8 * 16;
            const __nv_bfloat16* src =
                (isB ? B + (size_t)row * ldk : A + (size_t)row * ldk) + k + c8 * 8;
            cpasync16(dst, src);
        }
    };

    load_tile(0, 0);
    CP_COMMIT();
    if (ktiles > 1) { load_tile(1, 1); }
    CP_COMMIT();

    const uint32_t rsel = lane & 15;
    const uint32_t chi = (lane >> 4) * 16;

    uint32_t aF[2][2][4];
    uint32_t bF[2][4][2];

    auto ld_frags = [&](int fb, uint32_t sA, uint32_t sB, int ks) {
        uint32_t colB = ks * 32 + chi;
#pragma unroll
        for (int mt = 0; mt < 2; mt++) {
            uint32_t addr = sA + (wm * 32 + mt * 16 + rsel) * RSTRIDE + colB;
            ldsm_x4(aF[fb][mt][0], aF[fb][mt][1], aF[fb][mt][2], aF[fb][mt][3], addr);
        }
#pragma unroll
        for (int p = 0; p < 2; p++) {
            uint32_t r0, r1, r2, r3;
            uint32_t addr = sB + (wn * 32 + p * 16 + rsel) * RSTRIDE + colB;
            ldsm_x4(r0, r1, r2, r3, addr);
            bF[fb][2 * p][0] = r0; bF[fb][2 * p][1] = r2;
            bF[fb][2 * p + 1][0] = r1; bF[fb][2 * p + 1][1] = r3;
        }
    };
    auto do_mma = [&](int fb) {
#pragma unroll
        for (int mt = 0; mt < 2; mt++)
#pragma unroll
            for (int nt = 0; nt < 4; nt++)
                mma_bf16(acc[mt][nt], aF[fb][mt], bF[fb][nt]);
    };

    for (int t = 0; t < ktiles; t++) {
        if (t + 1 < ktiles)
            asm volatile("cp.async.wait_group 1;\n" ::: "memory");
        else
            asm volatile("cp.async.wait_group 0;\n" ::: "memory");
        __syncthreads();

        int buf = t & 1;
        uint32_t sA = sbase + buf * BUFSZ;
        uint32_t sB = sA + A_ROWS * RSTRIDE;

        ld_frags(0, sA, sB, 0);
        ld_frags(1, sA, sB, 1);
        do_mma(0);
        ld_frags(0, sA, sB, 2);
        do_mma(1);
        ld_frags(1, sA, sB, 3);
        do_mma(0);
        __syncthreads();
        if (t + 2 < ktiles) {
            load_tile(buf, t + 2);
            CP_COMMIT();
        }
        do_mma(1);
    }

    const int mrow = lane >> 2, ncol = (lane & 3) * 2;
#pragma unroll
    for (int mt = 0; mt < 2; mt++)
#pragma unroll
        for (int nt = 0; nt < 4; nt++) {
            int m = wm * 32 + mt * 16 + mrow;
            int n = wn * 32 + nt * 8 + ncol;
            store_c(&C[(size_t)n * ldC + m],           acc[mt][nt][0]);
            store_c(&C[(size_t)(n + 1) * ldC + m],     acc[mt][nt][1]);
            store_c(&C[(size_t)n * ldC + m + 8],       acc[mt][nt][2]);
            store_c(&C[(size_t)(n + 1) * ldC + m + 8], acc[mt][nt][3]);
        }
}

// segmented GEMM1: 4 class-segments in one launch. 292 CTAs.
__global__ __launch_bounds__(256) void gemm_seg_k() {
    extern __shared__ __align__(128) char smem_raw[];
    uint32_t sbase = smem_u32(smem_raw);
    int bid = blockIdx.x;
    int seg = (bid < 28) ? 0 : (bid < 88) ? 1 : (bid < 148) ? 2 : 3;
    const int segStart[4] = {0, 28, 88, 148};
    const int segMt[4]    = {4, 12, 12, 36};
    const int segArow[4]  = {0, 512, 2048, 3584};
    const int segBrow[4]  = {0, 448, 768, 1088};
    const int segCoff[4]  = {P_II_OFF, P_EI_OFF, P_IE_OFF, P_EE_OFF};
    const int segLd[4]    = {512, 1536, 1536, 4608};
    int local = bid - segStart[seg];
    int bx = local % segMt[seg], by = local / segMt[seg];
    int m0 = bx * 128, n0 = by * 64;
    const __nv_bfloat16* A = g_Aall + (size_t)(segArow[seg] + m0) * K1;
    const __nv_bfloat16* B = g_Bx2 + (size_t)(segBrow[seg] + n0) * K1;
    __nv_bfloat16* C = g_Pcat + segCoff[seg] + (size_t)n0 * segLd[seg] + m0;
    gemm_core<__nv_bfloat16>(A, B, C, K1, K1 / 64, segLd[seg], sbase);
}

// GEMM2 split-K
__global__ __launch_bounds__(256) void gemm2_k() {
    extern __shared__ __align__(128) char smem_raw[];
    uint32_t sbase = smem_u32(smem_raw);
    int m0 = blockIdx.x * 128, n0 = blockIdx.y * 64;
    int z = blockIdx.z;
    int kt = K2 / KSPLIT / 64;   // 6
    const __nv_bfloat16* A = g_W2b + (size_t)m0 * K2 + z * kt * 64;
    const __nv_bfloat16* B = g_Tbb + (size_t)n0 * K2 + z * kt * 64;
    float* C = g_part + (size_t)z * NPAD * OC2 + (size_t)n0 * OC2 + m0;
    gemm_core<float>(A, B, C, K2, kt, OC2, sbase);
}

// ---------------- sparse per-label accumulation via pixel lists -> g_Tbb[bl][k] ----------------
__global__ __launch_bounds__(512) void acc_kernel(const float* __restrict__ b1) {
    const int bl = blockIdx.x;
    const int b = bl / NL;
    const int oc1 = threadIdx.x;

    const int lo[3][3] = {{0, 0, 1}, {0, 0, 1}, {3, 4, 5}};
    const int hi[3][3] = {{18, 19, 20}, {22, 23, 23}, {22, 23, 23}};

    float T9[9];
#pragma unroll
    for (int k = 0; k < 9; k++) T9[k] = 0.f;

    const int cnt = g_cnt[bl];
    const unsigned short* plist = &g_plist[bl * NPIX];

    for (int i = 0; i < cnt; i++) {
        int pix = plist[i];
        int p = pix / 24, q = pix % 24;
        bool Ip = (p >= 5 && p <= 18), Iq = (q >= 5 && q <= 18);
        int rep = (p < 5) ? p : p - 14;
        int req = (q < 5) ? q : q - 14;

        if (Ip && Iq) {
            int slot = b * 196 + (p - 5) * 14 + (q - 5);
            float s = __bfloat162float(g_Pcat[P_II_OFF + (size_t)slot * 512 + oc1]);
#pragma unroll
            for (int k = 0; k < 9; k++) T9[k] += s;
        } else if (!Ip && Iq) {
            int slot = b * 140 + rep * 14 + (q - 5);
            const __nv_bfloat16* v = &g_Pcat[P_EI_OFF + (size_t)slot * 1536 + oc1 * 3];
            float ra[3];
#pragma unroll
            for (int a = 0; a < 3; a++) ra[a] = __bfloat162float(v[a]);
#pragma unroll
            for (int dr = 0; dr < 3; dr++) {
                float s = 0.f;
#pragma unroll
                for (int a = 0; a < 3; a++)
                    if (p >= lo[dr][a] && p <= hi[dr][a]) s += ra[a];
                T9[dr * 3 + 0] += s; T9[dr * 3 + 1] += s; T9[dr * 3 + 2] += s;
            }
        } else if (Ip) {
            int slot = b * 140 + (p - 5) * 10 + req;
            const __nv_bfloat16* v = &g_Pcat[P_IE_OFF + (size_t)slot * 1536 + oc1 * 3];
            float rb[3];
#pragma unroll
            for (int bb = 0; bb < 3; bb++) rb[bb] = __bfloat162float(v[bb]);
#pragma unroll
            for (int dc = 0; dc < 3; dc++) {
                float s = 0.f;
#pragma unroll
                for (int bb = 0; bb < 3; bb++)
                    if (q >= lo[dc][bb] && q <= hi[dc][bb]) s += rb[bb];
                T9[0 + dc] += s; T9[3 + dc] += s; T9[6 + dc] += s;
            }
        } else {
            int slot = b * 100 + rep * 10 + req;
            const __nv_bfloat16* v = &g_Pcat[P_EE_OFF + (size_t)slot * 4608 + oc1 * 9];
            float vv[9];
#pragma unroll
            for (int t = 0; t < 9; t++) vv[t] = __bfloat162float(v[t]);
            float rs[3][3];
#pragma unroll
            for (int dr = 0; dr < 3; dr++)
#pragma unroll
                for (int bb = 0; bb < 3; bb++) {
                    float s = 0.f;
#pragma unroll
                    for (int a = 0; a < 3; a++)
                        if (p >= lo[dr][a] && p <= hi[dr][a]) s += vv[a * 3 + bb];
                    rs[dr][bb] = s;
                }
#pragma unroll
            for (int dr = 0; dr < 3; dr++)
#pragma unroll
                for (int dc = 0; dc < 3; dc++) {
                    float s = 0.f;
#pragma unroll
                    for (int bb = 0; bb < 3; bb++)
                        if (q >= lo[dc][bb] && q <= hi[dc][bb]) s += rs[dr][bb];
                    T9[dr * 3 + dc] += s;
                }
        }
    }

    const float nrc[3] = {20.f, 24.f, 20.f};
    float bb1 = b1[oc1];
#pragma unroll
    for (int k = 0; k < 9; k++) {
        float t = (T9[k] + nrc[k / 3] * nrc[k % 3] * bb1) * (1.0f / 576.0f);
        g_Tbb[(size_t)bl * K2 + oc1 * 9 + k] = __float2bfloat16(t);
    }
}

// ---------------- fused reduce + expand (float4 stores) ----------------
__global__ __launch_bounds__(512) void expand2_k(const float* __restrict__ w3,
                                                 const float* __restrict__ b3,
                                                 const float* __restrict__ b2,
                                                 float4* __restrict__ out) {
    __shared__ float ssum[512];
    int bl = blockIdx.x;
    int b = bl / NL, l = bl % NL;
    int c = threadIdx.x;
    const int S = NPAD * OC2;
    float s = b2[c];
#pragma unroll
    for (int z = 0; z < KSPLIT; z++) s += g_part[(size_t)z * S + bl * OC2 + c];
    ssum[c] = s;
    __syncthreads();

    int c4 = threadIdx.x & 127;
    int grp = threadIdx.x >> 7;
    float4 sv = *(const float4*)&ssum[c4 * 4];
    size_t base4 = (((size_t)b * 77 * NL + l) * 512) / 4 + c4;
    for (int o = grp; o < 77; o += 4) {
        float w = __ldg(&w3[o]), bb = __ldg(&b3[o]);
        float4 r = make_float4(w * sv.x + bb, w * sv.y + bb, w * sv.z + bb, w * sv.w + bb);
        __stcs(&out[base4 + (size_t)o * NL * 128], r);
    }
}

// ---------------- launch ----------------
extern "C" void kernel_launch(void* const* d_in, const int* in_sizes, int n_in,
                              void* d_out, int out_size) {
    const float* noise   = (const float*)d_in[0];
    const int*   targets = (const int*)  d_in[1];
    const float* w1      = (const float*)d_in[2];
    const float* b1      = (const float*)d_in[3];
    const float* w2      = (const float*)d_in[4];
    const float* b2      = (const float*)d_in[5];
    const float* w3      = (const float*)d_in[6];
    const float* b3      = (const float*)d_in[7];
    float* out      = (float*)d_out;
    float* out_img  = out;
    float* out_text = out + IMG_ELEMS;

    cudaFuncSetAttribute(gemm_seg_k, cudaFuncAttributeMaxDynamicSharedMemorySize, SMEM_SZ);
    cudaFuncSetAttribute(gemm2_k,    cudaFuncAttributeMaxDynamicSharedMemorySize, SMEM_SZ);

    // order: 4th launch (ncu -s 5 target) = acc_kernel (verify the fix).
    plist_k<<<B_, NPIX>>>(targets);                                        // 1
    prepA_k<<<XPACK_BLOCKS + 512, 256>>>(noise, w1);                       // 2
    gemm_seg_k<<<292, 256, SMEM_SZ>>>();                                   // 3
    acc_kernel<<<NBL, 512>>>(b1);                                          // 4 (profiled)
    prepB_k<<<W2B_BLOCKS + 912, 256>>>((const float4*)w2, noise, out_img); // 5
    gemm2_k<<<dim3(OC2 / 128, NPAD / 64, KSPLIT), 256, SMEM_SZ>>>();       // 6
    expand2_k<<<NBL, 512>>>(w3, b3, b2, (float4*)out_text);                // 7
}

// round 13
// speedup vs baseline: 1.5409x; 1.0214x over previous
#include <cuda_runtime.h>
#include <cuda_bf16.h>
#include <cstdint>

// ---------------- problem constants ----------------
#define B_      2
#define NPIX    576
#define NL      171
#define NBL     342
#define NPAD    384
#define ICH     768
#define OC1     512
#define OC2     512
#define K1      768
#define K2      4608
#define KSPLIT  12
#define IMG_ELEMS  (577*B_*768)
#define TXT_ELEMS  (B_*77*NL*512)

// pixel classes: interior rows/cols = [5,18] (14), edge = 10
#define BX_ROWS 1344
#define AROWS   8192
#define P_II_OFF 0
#define P_EI_OFF 229376
#define P_IE_OFF 720896
#define P_EE_OFF 1212416
#define P_TOTAL  2392064
#define PL_STRIDE 580      // 576 + up to 3 sentinel pads, 8B-aligned

// ---------------- scratch ----------------
__device__ __align__(128) __nv_bfloat16 g_Aall[(size_t)AROWS * K1];
__device__ __align__(128) __nv_bfloat16 g_Bx2[(size_t)BX_ROWS * K1];
__device__ __align__(128) __nv_bfloat16 g_Pcat[P_TOTAL];
__device__ __align__(128) __nv_bfloat16 g_W2b[OC2 * K2];
__device__ __align__(128) __nv_bfloat16 g_Tbb[NPAD * K2];
__device__ __align__(128) float         g_part[KSPLIT * NPAD * OC2];
__device__ unsigned short g_plist[NBL * PL_STRIDE];
__device__ int            g_cnt[NBL];

// ---------------- PTX helpers ----------------
__device__ __forceinline__ uint32_t smem_u32(const void* p) {
    uint32_t a;
    asm("{ .reg .u64 t; cvta.to.shared.u64 t, %1; cvt.u32.u64 %0, t; }" : "=r"(a) : "l"(p));
    return a;
}
__device__ __forceinline__ void cpasync16(uint32_t dst, const void* src) {
    asm volatile("cp.async.cg.shared.global [%0], [%1], 16;\n" :: "r"(dst), "l"(src));
}
#define CP_COMMIT() asm volatile("cp.async.commit_group;\n" ::: "memory")

__device__ __forceinline__ void ldsm_x4(uint32_t& r0, uint32_t& r1, uint32_t& r2,
                                        uint32_t& r3, uint32_t addr) {
    asm volatile("ldmatrix.sync.aligned.m8n8.x4.shared.b16 {%0,%1,%2,%3}, [%4];"
                 : "=r"(r0), "=r"(r1), "=r"(r2), "=r"(r3) : "r"(addr));
}
__device__ __forceinline__ void mma_bf16(float* c, const uint32_t* a, const uint32_t* b) {
    asm volatile("mma.sync.aligned.m16n8k16.row.col.f32.bf16.bf16.f32 "
                 "{%0,%1,%2,%3}, {%4,%5,%6,%7}, {%8,%9}, {%0,%1,%2,%3};"
                 : "+f"(c[0]), "+f"(c[1]), "+f"(c[2]), "+f"(c[3])
                 : "r"(a[0]), "r"(a[1]), "r"(a[2]), "r"(a[3]), "r"(b[0]), "r"(b[1]));
}
__device__ __forceinline__ void store_c(float* p, float v) { *p = v; }
__device__ __forceinline__ void store_c(__nv_bfloat16* p, float v) { *p = __float2bfloat16(v); }

// pixel -> B-matrix row (class-sorted layout)
__device__ __forceinline__ int browmap(int b, int pix) {
    int p = pix / 24, q = pix % 24;
    bool Ip = (p >= 5 && p <= 18), Iq = (q >= 5 && q <= 18);
    int rep = (p < 5) ? p : p - 14;
    int req = (q < 5) ? q : q - 14;
    if (Ip && Iq)  return        b * 196 + (p - 5) * 14 + (q - 5);
    if (!Ip && Iq) return 448 +  b * 140 + rep * 14 + (q - 5);
    if (Ip)        return 768 +  b * 140 + (p - 5) * 10 + req;
    return 1088 + b * 100 + rep * 10 + req;
}

// ---------------- fused prep A: xpack (864) + weight build (512) + plist (2) ----------------
#define XPACK_BLOCKS (18 * 24 * 2)
#define PREPA_BLOCKS (XPACK_BLOCKS + 512 + B_)
__global__ __launch_bounds__(256) void prepA_k(const float* __restrict__ noise,
                                               const float* __restrict__ w1,
                                               const int* __restrict__ targets) {
    int bid = blockIdx.x;
    if (bid < XPACK_BLOCKS) {
        __shared__ float tile[32][33];
        int b = bid / (18 * 24);
        int r0 = bid % (18 * 24);
        int p0 = (r0 % 18) * 32, c0 = (r0 / 18) * 32;
        int tx = threadIdx.x & 31, ty = threadIdx.x >> 5;
        for (int r = ty; r < 32; r += 8)
            tile[r][tx] = noise[(size_t)b * 443136 + (c0 + r) * 577 + 1 + p0 + tx];
        __syncthreads();
        for (int r = ty; r < 32; r += 8) {
            int dstrow = browmap(b, p0 + r);
            g_Bx2[(size_t)dstrow * K1 + c0 + tx] = __float2bfloat16(tile[tx][r]);
        }
    } else if (bid < XPACK_BLOCKS + 512) {
        __shared__ float sm[ICH * 9];
        int oc1 = bid - XPACK_BLOCKS;
        const float4* src = (const float4*)(w1 + (size_t)oc1 * ICH * 9);
        for (int i = threadIdx.x; i < ICH * 9 / 4; i += 256)
            ((float4*)sm)[i] = src[i];
        __syncthreads();
        for (int ic = threadIdx.x; ic < ICH; ic += 256) {
            float v[9];
#pragma unroll
            for (int t = 0; t < 9; t++) v[t] = sm[ic * 9 + t];
            float s9 = 0.f, va[3] = {0, 0, 0}, vb[3] = {0, 0, 0};
#pragma unroll
            for (int a = 0; a < 3; a++)
#pragma unroll
                for (int bb = 0; bb < 3; bb++) {
                    float x = v[a * 3 + bb];
                    s9 += x; va[a] += x; vb[bb] += x;
                }
            g_Aall[(size_t)oc1 * K1 + ic] = __float2bfloat16(s9);
#pragma unroll
            for (int a = 0; a < 3; a++)
                g_Aall[(size_t)(512 + oc1 * 3 + a) * K1 + ic] = __float2bfloat16(va[a]);
#pragma unroll
            for (int bb = 0; bb < 3; bb++)
                g_Aall[(size_t)(2048 + oc1 * 3 + bb) * K1 + ic] = __float2bfloat16(vb[bb]);
#pragma unroll
            for (int t = 0; t < 9; t++)
                g_Aall[(size_t)(3584 + oc1 * 9 + t) * K1 + ic] = __float2bfloat16(v[t]);
        }
    } else {
        // per-(b,l) pixel lists, ascending pixel order (bit-identical accumulation order)
        __shared__ int msh[NPIX];
        int b = bid - (XPACK_BLOCKS + 512);
        for (int p = threadIdx.x; p < NPIX; p += 256) {
            int pi = p / 24, qj = p % 24;
            msh[p] = targets[b * 147456 + (pi * 16) * 384 + qj * 16];
        }
        __syncthreads();
        int l = threadIdx.x;
        if (l < NL) {
            int bl = b * NL + l;
            int base = bl * PL_STRIDE;
            int cnt = 0;
            for (int p = 0; p < NPIX; p++)
                if (msh[p] == l) g_plist[base + cnt++] = (unsigned short)p;
            g_cnt[bl] = cnt;
            int cnt4 = (cnt + 3) & ~3;
            for (int jj = cnt; jj < cnt4; jj++) g_plist[base + jj] = 0xFFFF;
        }
    }
}

// ---------------- GEMM core (BK=64, 2-stage, frag double-buffer) ----------------
#define RSTRIDE 144
#define A_ROWS  128
#define B_ROWS  64
#define BUFSZ   ((A_ROWS + B_ROWS) * RSTRIDE)   // 27648
#define SMEM_SZ (2 * BUFSZ)                     // 55296

template <typename OutT>
__device__ __forceinline__ void gemm_core(
    const __nv_bfloat16* __restrict__ A,
    const __nv_bfloat16* __restrict__ B,
    OutT* __restrict__ C,
    int ldk, int ktiles, int ldC, uint32_t sbase)
{
    const int tid = threadIdx.x;
    const int lane = tid & 31, wid = tid >> 5;
    const int wm = wid & 3, wn = wid >> 2;

    float acc[2][4][4];
#pragma unroll
    for (int i = 0; i < 2; i++)
#pragma unroll
        for (int j = 0; j < 4; j++)
#pragma unroll
            for (int q = 0; q < 4; q++) acc[i][j][q] = 0.f;

    auto load_tile = [&](int buf, int t) {
        uint32_t s = sbase + buf * BUFSZ;
        int k = t * 64;
#pragma unroll
        for (int i = 0; i < 6; i++) {
            int ch = tid + i * 256;
            int isB = ch >> 10;
            int row = (ch >> 3) & (isB ? 63 : 127);
            int c8 = ch & 7;
            uint32_t dst = s + isB * (A_ROWS * RSTRIDE) + row * RSTRIDE + c8 * 16;
            const __nv_bfloat16* src =
                (isB ? B + (size_t)row * ldk : A + (size_t)row * ldk) + k + c8 * 8;
            cpasync16(dst, src);
        }
    };

    load_tile(0, 0);
    CP_COMMIT();
    if (ktiles > 1) { load_tile(1, 1); }
    CP_COMMIT();

    const uint32_t rsel = lane & 15;
    const uint32_t chi = (lane >> 4) * 16;

    uint32_t aF[2][2][4];
    uint32_t bF[2][4][2];

    auto ld_frags = [&](int fb, uint32_t sA, uint32_t sB, int ks) {
        uint32_t colB = ks * 32 + chi;
#pragma unroll
        for (int mt = 0; mt < 2; mt++) {
            uint32_t addr = sA + (wm * 32 + mt * 16 + rsel) * RSTRIDE + colB;
            ldsm_x4(aF[fb][mt][0], aF[fb][mt][1], aF[fb][mt][2], aF[fb][mt][3], addr);
        }
#pragma unroll
        for (int p = 0; p < 2; p++) {
            uint32_t r0, r1, r2, r3;
            uint32_t addr = sB + (wn * 32 + p * 16 + rsel) * RSTRIDE + colB;
            ldsm_x4(r0, r1, r2, r3, addr);
            bF[fb][2 * p][0] = r0; bF[fb][2 * p][1] = r2;
            bF[fb][2 * p + 1][0] = r1; bF[fb][2 * p + 1][1] = r3;
        }
    };
    auto do_mma = [&](int fb) {
#pragma unroll
        for (int mt = 0; mt < 2; mt++)
#pragma unroll
            for (int nt = 0; nt < 4; nt++)
                mma_bf16(acc[mt][nt], aF[fb][mt], bF[fb][nt]);
    };

    for (int t = 0; t < ktiles; t++) {
        if (t + 1 < ktiles)
            asm volatile("cp.async.wait_group 1;\n" ::: "memory");
        else
            asm volatile("cp.async.wait_group 0;\n" ::: "memory");
        __syncthreads();

        int buf = t & 1;
        uint32_t sA = sbase + buf * BUFSZ;
        uint32_t sB = sA + A_ROWS * RSTRIDE;

        ld_frags(0, sA, sB, 0);
        ld_frags(1, sA, sB, 1);
        do_mma(0);
        ld_frags(0, sA, sB, 2);
        do_mma(1);
        ld_frags(1, sA, sB, 3);
        do_mma(0);
        __syncthreads();
        if (t + 2 < ktiles) {
            load_tile(buf, t + 2);
            CP_COMMIT();
        }
        do_mma(1);
    }

    const int mrow = lane >> 2, ncol = (lane & 3) * 2;
#pragma unroll
    for (int mt = 0; mt < 2; mt++)
#pragma unroll
        for (int nt = 0; nt < 4; nt++) {
            int m = wm * 32 + mt * 16 + mrow;
            int n = wn * 32 + nt * 8 + ncol;
            store_c(&C[(size_t)n * ldC + m],           acc[mt][nt][0]);
            store_c(&C[(size_t)(n + 1) * ldC + m],     acc[mt][nt][1]);
            store_c(&C[(size_t)n * ldC + m + 8],       acc[mt][nt][2]);
            store_c(&C[(size_t)(n + 1) * ldC + m + 8], acc[mt][nt][3]);
        }
}

// ---------------- fused GEMM1 + prepB:
//   blocks [0,292): segmented GEMM1; [292,2596): w2 cast; [2596,3508): img transpose
#define GEMM1_BLOCKS 292
#define GEMMA_BLOCKS (GEMM1_BLOCKS + 2304 + 912)
__global__ __launch_bounds__(256) void gemmA_k(const float4* __restrict__ w2,
                                               const float* __restrict__ noise,
                                               float* __restrict__ out_img) {
    extern __shared__ __align__(128) char smem_raw[];
    int bid = blockIdx.x;
    if (bid < GEMM1_BLOCKS) {
        uint32_t sbase = smem_u32(smem_raw);
        int seg = (bid < 28) ? 0 : (bid < 88) ? 1 : (bid < 148) ? 2 : 3;
        const int segStart[4] = {0, 28, 88, 148};
        const int segMt[4]    = {4, 12, 12, 36};
        const int segArow[4]  = {0, 512, 2048, 3584};
        const int segBrow[4]  = {0, 448, 768, 1088};
        const int segCoff[4]  = {P_II_OFF, P_EI_OFF, P_IE_OFF, P_EE_OFF};
        const int segLd[4]    = {512, 1536, 1536, 4608};
        int local = bid - segStart[seg];
        int bx = local % segMt[seg], by = local / segMt[seg];
        int m0 = bx * 128, n0 = by * 64;
        const __nv_bfloat16* A = g_Aall + (size_t)(segArow[seg] + m0) * K1;
        const __nv_bfloat16* B = g_Bx2 + (size_t)(segBrow[seg] + n0) * K1;
        __nv_bfloat16* C = g_Pcat + segCoff[seg] + (size_t)n0 * segLd[seg] + m0;
        gemm_core<__nv_bfloat16>(A, B, C, K1, K1 / 64, segLd[seg], sbase);
    } else if (bid < GEMM1_BLOCKS + 2304) {
        int i = (bid - GEMM1_BLOCKS) * 256 + threadIdx.x;
        float4 v = w2[i];
        __nv_bfloat162 lo, hi;
        lo.x = __float2bfloat16(v.x); lo.y = __float2bfloat16(v.y);
        hi.x = __float2bfloat16(v.z); hi.y = __float2bfloat16(v.w);
        uint2 o;
        o.x = *(uint32_t*)&lo; o.y = *(uint32_t*)&hi;
        ((uint2*)g_W2b)[i] = o;
    } else {
        float (*tile)[33] = (float(*)[33])smem_raw;
        int t = bid - (GEMM1_BLOCKS + 2304);     // 0..911 = 19*24*2
        int b = t / (19 * 24);
        int r0 = t % (19 * 24);
        int s0 = (r0 % 19) * 32, c0 = (r0 / 19) * 32;
        int tx = threadIdx.x & 31, ty = threadIdx.x >> 5;
        for (int r = ty; r < 32; r += 8) {
            int s = s0 + tx;
            if (s < 577) tile[r][tx] = noise[(size_t)b * 443136 + (c0 + r) * 577 + s];
        }
        __syncthreads();
        for (int r = ty; r < 32; r += 8) {
            int s = s0 + r;
            if (s < 577) out_img[(size_t)s * (B_ * 768) + b * 768 + c0 + tx] = tile[tx][r];
        }
    }
}

// GEMM2 split-K
__global__ __launch_bounds__(256) void gemm2_k() {
    extern __shared__ __align__(128) char smem_raw[];
    uint32_t sbase = smem_u32(smem_raw);
    int m0 = blockIdx.x * 128, n0 = blockIdx.y * 64;
    int z = blockIdx.z;
    int kt = K2 / KSPLIT / 64;   // 6
    const __nv_bfloat16* A = g_W2b + (size_t)m0 * K2 + z * kt * 64;
    const __nv_bfloat16* B = g_Tbb + (size_t)n0 * K2 + z * kt * 64;
    float* C = g_part + (size_t)z * NPAD * OC2 + (size_t)n0 * OC2 + m0;
    gemm_core<float>(A, B, C, K2, kt, OC2, sbase);
}

// ---------------- sparse per-label accumulation (lists, unroll-4 sentinel) ----------------
__global__ __launch_bounds__(512) void acc_kernel(const float* __restrict__ b1) {
    const int bl = blockIdx.x;
    const int b = bl / NL;
    const int oc1 = threadIdx.x;

    const int lo[3][3] = {{0, 0, 1}, {0, 0, 1}, {3, 4, 5}};
    const int hi[3][3] = {{18, 19, 20}, {22, 23, 23}, {22, 23, 23}};

    float T9[9];
#pragma unroll
    for (int k = 0; k < 9; k++) T9[k] = 0.f;

    const int cnt4 = (g_cnt[bl] + 3) & ~3;
    const unsigned short* plist = &g_plist[bl * PL_STRIDE];

    for (int i = 0; i < cnt4; i += 4) {
#pragma unroll
        for (int j = 0; j < 4; j++) {
            int pix = plist[i + j];
            if (pix == 0xFFFF) continue;
            int p = pix / 24, q = pix % 24;
            bool Ip = (p >= 5 && p <= 18), Iq = (q >= 5 && q <= 18);
            int rep = (p < 5) ? p : p - 14;
            int req = (q < 5) ? q : q - 14;

            if (Ip && Iq) {
                int slot = b * 196 + (p - 5) * 14 + (q - 5);
                float s = __bfloat162float(g_Pcat[P_II_OFF + (size_t)slot * 512 + oc1]);
#pragma unroll
                for (int k = 0; k < 9; k++) T9[k] += s;
            } else if (!Ip && Iq) {
                int slot = b * 140 + rep * 14 + (q - 5);
                const __nv_bfloat16* v = &g_Pcat[P_EI_OFF + (size_t)slot * 1536 + oc1 * 3];
                float ra[3];
#pragma unroll
                for (int a = 0; a < 3; a++) ra[a] = __bfloat162float(v[a]);
#pragma unroll
                for (int dr = 0; dr < 3; dr++) {
                    float s = 0.f;
#pragma unroll
                    for (int a = 0; a < 3; a++)
                        if (p >= lo[dr][a] && p <= hi[dr][a]) s += ra[a];
                    T9[dr * 3 + 0] += s; T9[dr * 3 + 1] += s; T9[dr * 3 + 2] += s;
                }
            } else if (Ip) {
                int slot = b * 140 + (p - 5) * 10 + req;
                const __nv_bfloat16* v = &g_Pcat[P_IE_OFF + (size_t)slot * 1536 + oc1 * 3];
                float rb[3];
#pragma unroll
                for (int bb = 0; bb < 3; bb++) rb[bb] = __bfloat162float(v[bb]);
#pragma unroll
                for (int dc = 0; dc < 3; dc++) {
                    float s = 0.f;
#pragma unroll
                    for (int bb = 0; bb < 3; bb++)
                        if (q >= lo[dc][bb] && q <= hi[dc][bb]) s += rb[bb];
                    T9[0 + dc] += s; T9[3 + dc] += s; T9[6 + dc] += s;
                }
            } else {
                int slot = b * 100 + rep * 10 + req;
                const __nv_bfloat16* v = &g_Pcat[P_EE_OFF + (size_t)slot * 4608 + oc1 * 9];
                float vv[9];
#pragma unroll
                for (int t = 0; t < 9; t++) vv[t] = __bfloat162float(v[t]);
                float rs[3][3];
#pragma unroll
                for (int dr = 0; dr < 3; dr++)
#pragma unroll
                    for (int bb = 0; bb < 3; bb++) {
                        float s = 0.f;
#pragma unroll
                        for (int a = 0; a < 3; a++)
                            if (p >= lo[dr][a] && p <= hi[dr][a]) s += vv[a * 3 + bb];
                        rs[dr][bb] = s;
                    }
#pragma unroll
                for (int dr = 0; dr < 3; dr++)
#pragma unroll
                    for (int dc = 0; dc < 3; dc++) {
                        float s = 0.f;
#pragma unroll
                        for (int bb = 0; bb < 3; bb++)
                            if (q >= lo[dc][bb] && q <= hi[dc][bb]) s += rs[dr][bb];
                        T9[dr * 3 + dc] += s;
                    }
            }
        }
    }

    const float nrc[3] = {20.f, 24.f, 20.f};
    float bb1 = b1[oc1];
#pragma unroll
    for (int k = 0; k < 9; k++) {
        float t = (T9[k] + nrc[k / 3] * nrc[k % 3] * bb1) * (1.0f / 576.0f);
        g_Tbb[(size_t)bl * K2 + oc1 * 9 + k] = __float2bfloat16(t);
    }
}

// ---------------- fused reduce + expand (float4 stores) ----------------
__global__ __launch_bounds__(512) void expand2_k(const float* __restrict__ w3,
                                                 const float* __restrict__ b3,
                                                 const float* __restrict__ b2,
                                                 float4* __restrict__ out) {
    __shared__ float ssum[512];
    int bl = blockIdx.x;
    int b = bl / NL, l = bl % NL;
    int c = threadIdx.x;
    const int S = NPAD * OC2;
    float s = b2[c];
#pragma unroll
    for (int z = 0; z < KSPLIT; z++) s += g_part[(size_t)z * S + bl * OC2 + c];
    ssum[c] = s;
    __syncthreads();

    int c4 = threadIdx.x & 127;
    int grp = threadIdx.x >> 7;
    float4 sv = *(const float4*)&ssum[c4 * 4];
    size_t base4 = (((size_t)b * 77 * NL + l) * 512) / 4 + c4;
    for (int o = grp; o < 77; o += 4) {
        float w = __ldg(&w3[o]), bb = __ldg(&b3[o]);
        float4 r = make_float4(w * sv.x + bb, w * sv.y + bb, w * sv.z + bb, w * sv.w + bb);
        __stcs(&out[base4 + (size_t)o * NL * 128], r);
    }
}

// ---------------- launch ----------------
extern "C" void kernel_launch(void* const* d_in, const int* in_sizes, int n_in,
                              void* d_out, int out_size) {
    const float* noise   = (const float*)d_in[0];
    const int*   targets = (const int*)  d_in[1];
    const float* w1      = (const float*)d_in[2];
    const float* b1      = (const float*)d_in[3];
    const float* w2      = (const float*)d_in[4];
    const float* b2      = (const float*)d_in[5];
    const float* w3      = (const float*)d_in[6];
    const float* b3      = (const float*)d_in[7];
    float* out      = (float*)d_out;
    float* out_img  = out;
    float* out_text = out + IMG_ELEMS;

    cudaFuncSetAttribute(gemmA_k, cudaFuncAttributeMaxDynamicSharedMemorySize, SMEM_SZ);
    cudaFuncSetAttribute(gemm2_k, cudaFuncAttributeMaxDynamicSharedMemorySize, SMEM_SZ);

    prepA_k<<<PREPA_BLOCKS, 256>>>(noise, w1, targets);                  // 1
    gemmA_k<<<GEMMA_BLOCKS, 256, SMEM_SZ>>>((const float4*)w2, noise, out_img); // 2
    acc_kernel<<<NBL, 512>>>(b1);                                        // 3
    gemm2_k<<<dim3(OC2 / 128, NPAD / 64, KSPLIT), 256, SMEM_SZ>>>();     // 4 (profiled)
    expand2_k<<<NBL, 512>>>(w3, b3, b2, (float4*)out_text);              // 5
}

// round 14
// speedup vs baseline: 1.5494x; 1.0055x over previous
#include <cuda_runtime.h>
#include <cuda_bf16.h>
#include <cstdint>

// ---------------- problem constants ----------------
#define B_      2
#define NPIX    576
#define NL      171
#define NBL     342
#define NPAD    384
#define ICH     768
#define OC1     512
#define OC2     512
#define K1      768
#define K2      4608
#define KSPLIT  12
#define IMG_ELEMS  (577*B_*768)
#define TXT_ELEMS  (B_*77*NL*512)

// pixel classes: interior rows/cols = [5,18] (14), edge = 10
#define BX_ROWS 1344
#define AROWS   8192
#define P_II_OFF 0
#define P_EI_OFF 229376
#define P_IE_OFF 720896
#define P_EE_OFF 1212416
#define P_TOTAL  2392064
#define PL_STRIDE 580

// ---------------- scratch ----------------
__device__ __align__(128) __nv_bfloat16 g_Aall[(size_t)AROWS * K1];
__device__ __align__(128) __nv_bfloat16 g_Bx2[(size_t)BX_ROWS * K1];
__device__ __align__(128) __nv_bfloat16 g_Pcat[P_TOTAL];
__device__ __align__(128) __nv_bfloat16 g_W2b[OC2 * K2];
__device__ __align__(128) __nv_bfloat16 g_Tbb[NPAD * K2];
__device__ __align__(128) float         g_part[KSPLIT * NPAD * OC2];
__device__ unsigned short g_plist[NBL * PL_STRIDE];
__device__ int            g_cnt[NBL];

// ---------------- PTX helpers ----------------
__device__ __forceinline__ uint32_t smem_u32(const void* p) {
    uint32_t a;
    asm("{ .reg .u64 t; cvta.to.shared.u64 t, %1; cvt.u32.u64 %0, t; }" : "=r"(a) : "l"(p));
    return a;
}
__device__ __forceinline__ void cpasync16(uint32_t dst, const void* src) {
    asm volatile("cp.async.cg.shared.global [%0], [%1], 16;\n" :: "r"(dst), "l"(src));
}
#define CP_COMMIT() asm volatile("cp.async.commit_group;\n" ::: "memory")

__device__ __forceinline__ void ldsm_x4(uint32_t& r0, uint32_t& r1, uint32_t& r2,
                                        uint32_t& r3, uint32_t addr) {
    asm volatile("ldmatrix.sync.aligned.m8n8.x4.shared.b16 {%0,%1,%2,%3}, [%4];"
                 : "=r"(r0), "=r"(r1), "=r"(r2), "=r"(r3) : "r"(addr));
}
__device__ __forceinline__ void mma_bf16(float* c, const uint32_t* a, const uint32_t* b) {
    asm volatile("mma.sync.aligned.m16n8k16.row.col.f32.bf16.bf16.f32 "
                 "{%0,%1,%2,%3}, {%4,%5,%6,%7}, {%8,%9}, {%0,%1,%2,%3};"
                 : "+f"(c[0]), "+f"(c[1]), "+f"(c[2]), "+f"(c[3])
                 : "r"(a[0]), "r"(a[1]), "r"(a[2]), "r"(a[3]), "r"(b[0]), "r"(b[1]));
}
__device__ __forceinline__ void store_c(float* p, float v) { *p = v; }
__device__ __forceinline__ void store_c(__nv_bfloat16* p, float v) { *p = __float2bfloat16(v); }

// pixel -> B-matrix row (class-sorted layout)
__device__ __forceinline__ int browmap(int b, int pix) {
    int p = pix / 24, q = pix % 24;
    bool Ip = (p >= 5 && p <= 18), Iq = (q >= 5 && q <= 18);
    int rep = (p < 5) ? p : p - 14;
    int req = (q < 5) ? q : q - 14;
    if (Ip && Iq)  return        b * 196 + (p - 5) * 14 + (q - 5);
    if (!Ip && Iq) return 448 +  b * 140 + rep * 14 + (q - 5);
    if (Ip)        return 768 +  b * 140 + (p - 5) * 10 + req;
    return 1088 + b * 100 + rep * 10 + req;
}

// ---------------- acc per-pixel body (accumulates into T9) ----------------
__device__ __forceinline__ void acc_pixel(int b, int oc1, int pix, float* T9) {
    const int lo[3][3] = {{0, 0, 1}, {0, 0, 1}, {3, 4, 5}};
    const int hi[3][3] = {{18, 19, 20}, {22, 23, 23}, {22, 23, 23}};
    int p = pix / 24, q = pix % 24;
    bool Ip = (p >= 5 && p <= 18), Iq = (q >= 5 && q <= 18);
    int rep = (p < 5) ? p : p - 14;
    int req = (q < 5) ? q : q - 14;

    if (Ip && Iq) {
        int slot = b * 196 + (p - 5) * 14 + (q - 5);
        float s = __bfloat162float(g_Pcat[P_II_OFF + (size_t)slot * 512 + oc1]);
#pragma unroll
        for (int k = 0; k < 9; k++) T9[k] += s;
    } else if (!Ip && Iq) {
        int slot = b * 140 + rep * 14 + (q - 5);
        const __nv_bfloat16* v = &g_Pcat[P_EI_OFF + (size_t)slot * 1536 + oc1 * 3];
        float ra[3];
#pragma unroll
        for (int a = 0; a < 3; a++) ra[a] = __bfloat162float(v[a]);
#pragma unroll
        for (int dr = 0; dr < 3; dr++) {
            float s = 0.f;
#pragma unroll
            for (int a = 0; a < 3; a++)
                if (p >= lo[dr][a] && p <= hi[dr][a]) s += ra[a];
            T9[dr * 3 + 0] += s; T9[dr * 3 + 1] += s; T9[dr * 3 + 2] += s;
        }
    } else if (Ip) {
        int slot = b * 140 + (p - 5) * 10 + req;
        const __nv_bfloat16* v = &g_Pcat[P_IE_OFF + (size_t)slot * 1536 + oc1 * 3];
        float rb[3];
#pragma unroll
        for (int bb = 0; bb < 3; bb++) rb[bb] = __bfloat162float(v[bb]);
#pragma unroll
        for (int dc = 0; dc < 3; dc++) {
            float s = 0.f;
#pragma unroll
            for (int bb = 0; bb < 3; bb++)
                if (q >= lo[dc][bb] && q <= hi[dc][bb]) s += rb[bb];
            T9[0 + dc] += s; T9[3 + dc] += s; T9[6 + dc] += s;
        }
    } else {
        int slot = b * 100 + rep * 10 + req;
        const __nv_bfloat16* v = &g_Pcat[P_EE_OFF + (size_t)slot * 4608 + oc1 * 9];
        float vv[9];
#pragma unroll
        for (int t = 0; t < 9; t++) vv[t] = __bfloat162float(v[t]);
        float rs[3][3];
#pragma unroll
        for (int dr = 0; dr < 3; dr++)
#pragma unroll
            for (int bb = 0; bb < 3; bb++) {
                float s = 0.f;
#pragma unroll
                for (int a = 0; a < 3; a++)
                    if (p >= lo[dr][a] && p <= hi[dr][a]) s += vv[a * 3 + bb];
                rs[dr][bb] = s;
            }
#pragma unroll
        for (int dr = 0; dr < 3; dr++)
#pragma unroll
            for (int dc = 0; dc < 3; dc++) {
                float s = 0.f;
#pragma unroll
                for (int bb = 0; bb < 3; bb++)
                    if (q >= lo[dc][bb] && q <= hi[dc][bb]) s += rs[dr][bb];
                T9[dr * 3 + dc] += s;
            }
    }
}

// ---------------- fused prep A: xpack (864) + weight build (512) + plist (2) ----------------
#define XPACK_BLOCKS (18 * 24 * 2)
#define PREPA_BLOCKS (XPACK_BLOCKS + 512 + B_)
__global__ __launch_bounds__(256) void prepA_k(const float* __restrict__ noise,
                                               const float* __restrict__ w1,
                                               const int* __restrict__ targets) {
    int bid = blockIdx.x;
    if (bid < XPACK_BLOCKS) {
        __shared__ float tile[32][33];
        int b = bid / (18 * 24);
        int r0 = bid % (18 * 24);
        int p0 = (r0 % 18) * 32, c0 = (r0 / 18) * 32;
        int tx = threadIdx.x & 31, ty = threadIdx.x >> 5;
        for (int r = ty; r < 32; r += 8)
            tile[r][tx] = noise[(size_t)b * 443136 + (c0 + r) * 577 + 1 + p0 + tx];
        __syncthreads();
        for (int r = ty; r < 32; r += 8) {
            int dstrow = browmap(b, p0 + r);
            g_Bx2[(size_t)dstrow * K1 + c0 + tx] = __float2bfloat16(tile[tx][r]);
        }
    } else if (bid < XPACK_BLOCKS + 512) {
        __shared__ float sm[ICH * 9];
        int oc1 = bid - XPACK_BLOCKS;
        const float4* src = (const float4*)(w1 + (size_t)oc1 * ICH * 9);
        for (int i = threadIdx.x; i < ICH * 9 / 4; i += 256)
            ((float4*)sm)[i] = src[i];
        __syncthreads();
        for (int ic = threadIdx.x; ic < ICH; ic += 256) {
            float v[9];
#pragma unroll
            for (int t = 0; t < 9; t++) v[t] = sm[ic * 9 + t];
            float s9 = 0.f, va[3] = {0, 0, 0}, vb[3] = {0, 0, 0};
#pragma unroll
            for (int a = 0; a < 3; a++)
#pragma unroll
                for (int bb = 0; bb < 3; bb++) {
                    float x = v[a * 3 + bb];
                    s9 += x; va[a] += x; vb[bb] += x;
                }
            g_Aall[(size_t)oc1 * K1 + ic] = __float2bfloat16(s9);
#pragma unroll
            for (int a = 0; a < 3; a++)
                g_Aall[(size_t)(512 + oc1 * 3 + a) * K1 + ic] = __float2bfloat16(va[a]);
#pragma unroll
            for (int bb = 0; bb < 3; bb++)
                g_Aall[(size_t)(2048 + oc1 * 3 + bb) * K1 + ic] = __float2bfloat16(vb[bb]);
#pragma unroll
            for (int t = 0; t < 9; t++)
                g_Aall[(size_t)(3584 + oc1 * 9 + t) * K1 + ic] = __float2bfloat16(v[t]);
        }
    } else {
        __shared__ int msh[NPIX];
        int b = bid - (XPACK_BLOCKS + 512);
        for (int p = threadIdx.x; p < NPIX; p += 256) {
            int pi = p / 24, qj = p % 24;
            msh[p] = targets[b * 147456 + (pi * 16) * 384 + qj * 16];
        }
        __syncthreads();
        int l = threadIdx.x;
        if (l < NL) {
            int bl = b * NL + l;
            int base = bl * PL_STRIDE;
            int cnt = 0;
            for (int p = 0; p < NPIX; p++)
                if (msh[p] == l) g_plist[base + cnt++] = (unsigned short)p;
            g_cnt[bl] = cnt;
            if (cnt & 1) g_plist[base + cnt] = 0xFFFF;   // pad to even
        }
    }
}

// ---------------- GEMM core (BK=64, 2-stage, frag double-buffer) ----------------
#define RSTRIDE 144
#define A_ROWS  128
#define B_ROWS  64
#define BUFSZ   ((A_ROWS + B_ROWS) * RSTRIDE)   // 27648
#define SMEM_SZ (2 * BUFSZ)                     // 55296

template <typename OutT>
__device__ __forceinline__ void gemm_core(
    const __nv_bfloat16* __restrict__ A,
    const __nv_bfloat16* __restrict__ B,
    OutT* __restrict__ C,
    int ldk, int ktiles, int ldC, uint32_t sbase)
{
    const int tid = threadIdx.x;
    const int lane = tid & 31, wid = tid >> 5;
    const int wm = wid & 3, wn = wid >> 2;

    float acc[2][4][4];
#pragma unroll
    for (int i = 0; i < 2; i++)
#pragma unroll
        for (int j = 0; j < 4; j++)
#pragma unroll
            for (int q = 0; q < 4; q++) acc[i][j][q] = 0.f;

    auto load_tile = [&](int buf, int t) {
        uint32_t s = sbase + buf * BUFSZ;
        int k = t * 64;
#pragma unroll
        for (int i = 0; i < 6; i++) {
            int ch = tid + i * 256;
            int isB = ch >> 10;
            int row = (ch >> 3) & (isB ? 63 : 127);
            int c8 = ch & 7;
            uint32_t dst = s + isB * (A_ROWS * RSTRIDE) + row * RSTRIDE + c8 * 16;
            const __nv_bfloat16* src =
                (isB ? B + (size_t)row * ldk : A + (size_t)row * ldk) + k + c8 * 8;
            cpasync16(dst, src);
        }
    };

    load_tile(0, 0);
    CP_COMMIT();
    if (ktiles > 1) { load_tile(1, 1); }
    CP_COMMIT();

    const uint32_t rsel = lane & 15;
    const uint32_t chi = (lane >> 4) * 16;

    uint32_t aF[2][2][4];
    uint32_t bF[2][4][2];

    auto ld_frags = [&](int fb, uint32_t sA, uint32_t sB, int ks) {
        uint32_t colB = ks * 32 + chi;
#pragma unroll
        for (int mt = 0; mt < 2; mt++) {
            uint32_t addr = sA + (wm * 32 + mt * 16 + rsel) * RSTRIDE + colB;
            ldsm_x4(aF[fb][mt][0], aF[fb][mt][1], aF[fb][mt][2], aF[fb][mt][3], addr);
        }
#pragma unroll
        for (int p = 0; p < 2; p++) {
            uint32_t r0, r1, r2, r3;
            uint32_t addr = sB + (wn * 32 + p * 16 + rsel) * RSTRIDE + colB;
            ldsm_x4(r0, r1, r2, r3, addr);
            bF[fb][2 * p][0] = r0; bF[fb][2 * p][1] = r2;
            bF[fb][2 * p + 1][0] = r1; bF[fb][2 * p + 1][1] = r3;
        }
    };
    auto do_mma = [&](int fb) {
#pragma unroll
        for (int mt = 0; mt < 2; mt++)
#pragma unroll
            for (int nt = 0; nt < 4; nt++)
                mma_bf16(acc[mt][nt], aF[fb][mt], bF[fb][nt]);
    };

    for (int t = 0; t < ktiles; t++) {
        if (t + 1 < ktiles)
            asm volatile("cp.async.wait_group 1;\n" ::: "memory");
        else
            asm volatile("cp.async.wait_group 0;\n" ::: "memory");
        __syncthreads();

        int buf = t & 1;
        uint32_t sA = sbase + buf * BUFSZ;
        uint32_t sB = sA + A_ROWS * RSTRIDE;

        ld_frags(0, sA, sB, 0);
        ld_frags(1, sA, sB, 1);
        do_mma(0);
        ld_frags(0, sA, sB, 2);
        do_mma(1);
        ld_frags(1, sA, sB, 3);
        do_mma(0);
        __syncthreads();
        if (t + 2 < ktiles) {
            load_tile(buf, t + 2);
            CP_COMMIT();
        }
        do_mma(1);
    }

    const int mrow = lane >> 2, ncol = (lane & 3) * 2;
#pragma unroll
    for (int mt = 0; mt < 2; mt++)
#pragma unroll
        for (int nt = 0; nt < 4; nt++) {
            int m = wm * 32 + mt * 16 + mrow;
            int n = wn * 32 + nt * 8 + ncol;
            store_c(&C[(size_t)n * ldC + m],           acc[mt][nt][0]);
            store_c(&C[(size_t)(n + 1) * ldC + m],     acc[mt][nt][1]);
            store_c(&C[(size_t)n * ldC + m + 8],       acc[mt][nt][2]);
            store_c(&C[(size_t)(n + 1) * ldC + m + 8], acc[mt][nt][3]);
        }
}

// ---------------- fused GEMM1 + prepB ----------------
#define GEMM1_BLOCKS 292
#define GEMMA_BLOCKS (GEMM1_BLOCKS + 2304 + 912)
__global__ __launch_bounds__(256) void gemmA_k(const float4* __restrict__ w2,
                                               const float* __restrict__ noise,
                                               float* __restrict__ out_img) {
    extern __shared__ __align__(128) char smem_raw[];
    int bid = blockIdx.x;
    if (bid < GEMM1_BLOCKS) {
        uint32_t sbase = smem_u32(smem_raw);
        int seg = (bid < 28) ? 0 : (bid < 88) ? 1 : (bid < 148) ? 2 : 3;
        const int segStart[4] = {0, 28, 88, 148};
        const int segMt[4]    = {4, 12, 12, 36};
        const int segArow[4]  = {0, 512, 2048, 3584};
        const int segBrow[4]  = {0, 448, 768, 1088};
        const int segCoff[4]  = {P_II_OFF, P_EI_OFF, P_IE_OFF, P_EE_OFF};
        const int segLd[4]    = {512, 1536, 1536, 4608};
        int local = bid - segStart[seg];
        int bx = local % segMt[seg], by = local / segMt[seg];
        int m0 = bx * 128, n0 = by * 64;
        const __nv_bfloat16* A = g_Aall + (size_t)(segArow[seg] + m0) * K1;
        const __nv_bfloat16* B = g_Bx2 + (size_t)(segBrow[seg] + n0) * K1;
        __nv_bfloat16* C = g_Pcat + segCoff[seg] + (size_t)n0 * segLd[seg] + m0;
        gemm_core<__nv_bfloat16>(A, B, C, K1, K1 / 64, segLd[seg], sbase);
    } else if (bid < GEMM1_BLOCKS + 2304) {
        int i = (bid - GEMM1_BLOCKS) * 256 + threadIdx.x;
        float4 v = w2[i];
        __nv_bfloat162 lo, hi;
        lo.x = __float2bfloat16(v.x); lo.y = __float2bfloat16(v.y);
        hi.x = __float2bfloat16(v.z); hi.y = __float2bfloat16(v.w);
        uint2 o;
        o.x = *(uint32_t*)&lo; o.y = *(uint32_t*)&hi;
        ((uint2*)g_W2b)[i] = o;
    } else {
        float (*tile)[33] = (float(*)[33])smem_raw;
        int t = bid - (GEMM1_BLOCKS + 2304);
        int b = t / (19 * 24);
        int r0 = t % (19 * 24);
        int s0 = (r0 % 19) * 32, c0 = (r0 / 19) * 32;
        int tx = threadIdx.x & 31, ty = threadIdx.x >> 5;
        for (int r = ty; r < 32; r += 8) {
            int s = s0 + tx;
            if (s < 577) tile[r][tx] = noise[(size_t)b * 443136 + (c0 + r) * 577 + s];
        }
        __syncthreads();
        for (int r = ty; r < 32; r += 8) {
            int s = s0 + r;
            if (s < 577) out_img[(size_t)s * (B_ * 768) + b * 768 + c0 + tx] = tile[tx][r];
        }
    }
}

// GEMM2 split-K
__global__ __launch_bounds__(256) void gemm2_k() {
    extern __shared__ __align__(128) char smem_raw[];
    uint32_t sbase = smem_u32(smem_raw);
    int m0 = blockIdx.x * 128, n0 = blockIdx.y * 64;
    int z = blockIdx.z;
    int kt = K2 / KSPLIT / 64;   // 6
    const __nv_bfloat16* A = g_W2b + (size_t)m0 * K2 + z * kt * 64;
    const __nv_bfloat16* B = g_Tbb + (size_t)n0 * K2 + z * kt * 64;
    float* C = g_part + (size_t)z * NPAD * OC2 + (size_t)n0 * OC2 + m0;
    gemm_core<float>(A, B, C, K2, kt, OC2, sbase);
}

// ---------------- acc: dual accumulator (2 pixels in flight) ----------------
__global__ __launch_bounds__(512) void acc_kernel(const float* __restrict__ b1) {
    const int bl = blockIdx.x;
    const int b = bl / NL;
    const int oc1 = threadIdx.x;

    float T9a[9], T9b[9];
#pragma unroll
    for (int k = 0; k < 9; k++) { T9a[k] = 0.f; T9b[k] = 0.f; }

    const int cnt = g_cnt[bl];
    const unsigned short* plist = &g_plist[bl * PL_STRIDE];

    for (int i = 0; i < cnt; i += 2) {
        // one 4B load gives both pixel ids (list padded to even with 0xFFFF)
        uint32_t pair = *(const uint32_t*)&plist[i];
        int pix0 = pair & 0xFFFF;
        int pix1 = pair >> 16;
        // two independent bodies -> two loads in flight
        acc_pixel(b, oc1, pix0, T9a);
        if (pix1 != 0xFFFF) acc_pixel(b, oc1, pix1, T9b);
    }

    const float nrc[3] = {20.f, 24.f, 20.f};
    float bb1 = b1[oc1];
#pragma unroll
    for (int k = 0; k < 9; k++) {
        float t = (T9a[k] + T9b[k] + nrc[k / 3] * nrc[k % 3] * bb1) * (1.0f / 576.0f);
        g_Tbb[(size_t)bl * K2 + oc1 * 9 + k] = __float2bfloat16(t);
    }
}

// ---------------- fused reduce + expand (float4 stores) ----------------
__global__ __launch_bounds__(512) void expand2_k(const float* __restrict__ w3,
                                                 const float* __restrict__ b3,
                                                 const float* __restrict__ b2,
                                                 float4* __restrict__ out) {
    __shared__ float ssum[512];
    int bl = blockIdx.x;
    int b = bl / NL, l = bl % NL;
    int c = threadIdx.x;
    const int S = NPAD * OC2;
    float s = b2[c];
#pragma unroll
    for (int z = 0; z < KSPLIT; z++) s += g_part[(size_t)z * S + bl * OC2 + c];
    ssum[c] = s;
    __syncthreads();

    int c4 = threadIdx.x & 127;
    int grp = threadIdx.x >> 7;
    float4 sv = *(const float4*)&ssum[c4 * 4];
    size_t base4 = (((size_t)b * 77 * NL + l) * 512) / 4 + c4;
    for (int o = grp; o < 77; o += 4) {
        float w = __ldg(&w3[o]), bb = __ldg(&b3[o]);
        float4 r = make_float4(w * sv.x + bb, w * sv.y + bb, w * sv.z + bb, w * sv.w + bb);
        __stcs(&out[base4 + (size_t)o * NL * 128], r);
    }
}

// ---------------- launch ----------------
extern "C" void kernel_launch(void* const* d_in, const int* in_sizes, int n_in,
                              void* d_out, int out_size) {
    const float* noise   = (const float*)d_in[0];
    const int*   targets = (const int*)  d_in[1];
    const float* w1      = (const float*)d_in[2];
    const float* b1      = (const float*)d_in[3];
    const float* w2      = (const float*)d_in[4];
    const float* b2      = (const float*)d_in[5];
    const float* w3      = (const float*)d_in[6];
    const float* b3      = (const float*)d_in[7];
    float* out      = (float*)d_out;
    float* out_img  = out;
    float* out_text = out + IMG_ELEMS;

    cudaFuncSetAttribute(gemmA_k, cudaFuncAttributeMaxDynamicSharedMemorySize, SMEM_SZ);
    cudaFuncSetAttribute(gemm2_k, cudaFuncAttributeMaxDynamicSharedMemorySize, SMEM_SZ);

    prepA_k<<<PREPA_BLOCKS, 256>>>(noise, w1, targets);                  // 1
    gemmA_k<<<GEMMA_BLOCKS, 256, SMEM_SZ>>>((const float4*)w2, noise, out_img); // 2
    acc_kernel<<<NBL, 512>>>(b1);                                        // 3
    gemm2_k<<<dim3(OC2 / 128, NPAD / 64, KSPLIT), 256, SMEM_SZ>>>();     // 4 (profiled)
    expand2_k<<<NBL, 512>>>(w3, b3, b2, (float4*)out_text);              // 5
}

// round 15
// speedup vs baseline: 1.6992x; 1.0967x over previous
#include <cuda_runtime.h>
#include <cuda_bf16.h>
#include <cstdint>

// ---------------- problem constants ----------------
#define B_      2
#define NPIX    576
#define NL      171
#define NBL     342
#define NPAD    384
#define ICH     768
#define OC1     512
#define OC2     512
#define K1      768
#define K2      4608
#define KSPLIT  12
#define IMG_ELEMS  (577*B_*768)
#define TXT_ELEMS  (B_*77*NL*512)

// pixel classes: interior rows/cols = [5,18] (14), edge = 10
#define BX_ROWS 1344
#define AROWS   8192
#define P_II_OFF 0
#define P_EI_OFF 229376
#define P_IE_OFF 720896
#define P_EE_OFF 1212416
#define P_TOTAL  2392064
#define PL_STRIDE 580

// ---------------- scratch ----------------
__device__ __align__(128) __nv_bfloat16 g_Aall[(size_t)AROWS * K1];
__device__ __align__(128) __nv_bfloat16 g_Bx2[(size_t)BX_ROWS * K1];
__device__ __align__(128) __nv_bfloat16 g_Pcat[P_TOTAL];
__device__ __align__(128) __nv_bfloat16 g_W2b[OC2 * K2];
__device__ __align__(128) __nv_bfloat16 g_Tbb[NPAD * K2];
__device__ __align__(128) float         g_part[KSPLIT * NPAD * OC2];
__device__ unsigned short g_plist[NBL * PL_STRIDE];
__device__ int            g_cnt[NBL];

// ---------------- PTX helpers ----------------
__device__ __forceinline__ uint32_t smem_u32(const void* p) {
    uint32_t a;
    asm("{ .reg .u64 t; cvta.to.shared.u64 t, %1; cvt.u32.u64 %0, t; }" : "=r"(a) : "l"(p));
    return a;
}
__device__ __forceinline__ void cpasync16(uint32_t dst, const void* src) {
    asm volatile("cp.async.cg.shared.global [%0], [%1], 16;\n" :: "r"(dst), "l"(src));
}
#define CP_COMMIT() asm volatile("cp.async.commit_group;\n" ::: "memory")

__device__ __forceinline__ void ldsm_x4(uint32_t& r0, uint32_t& r1, uint32_t& r2,
                                        uint32_t& r3, uint32_t addr) {
    asm volatile("ldmatrix.sync.aligned.m8n8.x4.shared.b16 {%0,%1,%2,%3}, [%4];"
                 : "=r"(r0), "=r"(r1), "=r"(r2), "=r"(r3) : "r"(addr));
}
__device__ __forceinline__ void mma_bf16(float* c, const uint32_t* a, const uint32_t* b) {
    asm volatile("mma.sync.aligned.m16n8k16.row.col.f32.bf16.bf16.f32 "
                 "{%0,%1,%2,%3}, {%4,%5,%6,%7}, {%8,%9}, {%0,%1,%2,%3};"
                 : "+f"(c[0]), "+f"(c[1]), "+f"(c[2]), "+f"(c[3])
                 : "r"(a[0]), "r"(a[1]), "r"(a[2]), "r"(a[3]), "r"(b[0]), "r"(b[1]));
}
__device__ __forceinline__ void store_c(float* p, float v) { *p = v; }
__device__ __forceinline__ void store_c(__nv_bfloat16* p, float v) { *p = __float2bfloat16(v); }

// pixel -> B-matrix row (class-sorted layout)
__device__ __forceinline__ int browmap(int b, int pix) {
    int p = pix / 24, q = pix % 24;
    bool Ip = (p >= 5 && p <= 18), Iq = (q >= 5 && q <= 18);
    int rep = (p < 5) ? p : p - 14;
    int req = (q < 5) ? q : q - 14;
    if (Ip && Iq)  return        b * 196 + (p - 5) * 14 + (q - 5);
    if (!Ip && Iq) return 448 +  b * 140 + rep * 14 + (q - 5);
    if (Ip)        return 768 +  b * 140 + (p - 5) * 10 + req;
    return 1088 + b * 100 + rep * 10 + req;
}

// ---------------- acc per-pixel body ----------------
__device__ __forceinline__ void acc_pixel(int b, int oc1, int pix, float* T9) {
    const int lo[3][3] = {{0, 0, 1}, {0, 0, 1}, {3, 4, 5}};
    const int hi[3][3] = {{18, 19, 20}, {22, 23, 23}, {22, 23, 23}};
    int p = pix / 24, q = pix % 24;
    bool Ip = (p >= 5 && p <= 18), Iq = (q >= 5 && q <= 18);
    int rep = (p < 5) ? p : p - 14;
    int req = (q < 5) ? q : q - 14;

    if (Ip && Iq) {
        int slot = b * 196 + (p - 5) * 14 + (q - 5);
        float s = __bfloat162float(g_Pcat[P_II_OFF + (size_t)slot * 512 + oc1]);
#pragma unroll
        for (int k = 0; k < 9; k++) T9[k] += s;
    } else if (!Ip && Iq) {
        int slot = b * 140 + rep * 14 + (q - 5);
        const __nv_bfloat16* v = &g_Pcat[P_EI_OFF + (size_t)slot * 1536 + oc1 * 3];
        float ra[3];
#pragma unroll
        for (int a = 0; a < 3; a++) ra[a] = __bfloat162float(v[a]);
#pragma unroll
        for (int dr = 0; dr < 3; dr++) {
            float s = 0.f;
#pragma unroll
            for (int a = 0; a < 3; a++)
                if (p >= lo[dr][a] && p <= hi[dr][a]) s += ra[a];
            T9[dr * 3 + 0] += s; T9[dr * 3 + 1] += s; T9[dr * 3 + 2] += s;
        }
    } else if (Ip) {
        int slot = b * 140 + (p - 5) * 10 + req;
        const __nv_bfloat16* v = &g_Pcat[P_IE_OFF + (size_t)slot * 1536 + oc1 * 3];
        float rb[3];
#pragma unroll
        for (int bb = 0; bb < 3; bb++) rb[bb] = __bfloat162float(v[bb]);
#pragma unroll
        for (int dc = 0; dc < 3; dc++) {
            float s = 0.f;
#pragma unroll
            for (int bb = 0; bb < 3; bb++)
                if (q >= lo[dc][bb] && q <= hi[dc][bb]) s += rb[bb];
            T9[0 + dc] += s; T9[3 + dc] += s; T9[6 + dc] += s;
        }
    } else {
        int slot = b * 100 + rep * 10 + req;
        const __nv_bfloat16* v = &g_Pcat[P_EE_OFF + (size_t)slot * 4608 + oc1 * 9];
        float vv[9];
#pragma unroll
        for (int t = 0; t < 9; t++) vv[t] = __bfloat162float(v[t]);
        float rs[3][3];
#pragma unroll
        for (int dr = 0; dr < 3; dr++)
#pragma unroll
            for (int bb = 0; bb < 3; bb++) {
                float s = 0.f;
#pragma unroll
                for (int a = 0; a < 3; a++)
                    if (p >= lo[dr][a] && p <= hi[dr][a]) s += vv[a * 3 + bb];
                rs[dr][bb] = s;
            }
#pragma unroll
        for (int dr = 0; dr < 3; dr++)
#pragma unroll
            for (int dc = 0; dc < 3; dc++) {
                float s = 0.f;
#pragma unroll
                for (int bb = 0; bb < 3; bb++)
                    if (q >= lo[dc][bb] && q <= hi[dc][bb]) s += rs[dr][bb];
                T9[dr * 3 + dc] += s;
            }
    }
}

// ---------------- prep A: xpack (864) + w1r (512) + plist (2) + img transpose (912) ----------------
#define XPACK_BLOCKS (18 * 24 * 2)
#define IMG_BLOCKS (19 * 24 * 2)
#define PREPA_BLOCKS (XPACK_BLOCKS + 512 + B_ + IMG_BLOCKS)
__global__ __launch_bounds__(256) void prepA_k(const float* __restrict__ noise,
                                               const float* __restrict__ w1,
                                               const int* __restrict__ targets,
                                               float* __restrict__ out_img) {
    int bid = blockIdx.x;
    if (bid < XPACK_BLOCKS) {
        __shared__ float tile[32][33];
        int b = bid / (18 * 24);
        int r0 = bid % (18 * 24);
        int p0 = (r0 % 18) * 32, c0 = (r0 / 18) * 32;
        int tx = threadIdx.x & 31, ty = threadIdx.x >> 5;
        for (int r = ty; r < 32; r += 8)
            tile[r][tx] = noise[(size_t)b * 443136 + (c0 + r) * 577 + 1 + p0 + tx];
        __syncthreads();
        for (int r = ty; r < 32; r += 8) {
            int dstrow = browmap(b, p0 + r);
            g_Bx2[(size_t)dstrow * K1 + c0 + tx] = __float2bfloat16(tile[tx][r]);
        }
    } else if (bid < XPACK_BLOCKS + 512) {
        __shared__ float sm[ICH * 9];
        int oc1 = bid - XPACK_BLOCKS;
        const float4* src = (const float4*)(w1 + (size_t)oc1 * ICH * 9);
        for (int i = threadIdx.x; i < ICH * 9 / 4; i += 256)
            ((float4*)sm)[i] = src[i];
        __syncthreads();
        for (int ic = threadIdx.x; ic < ICH; ic += 256) {
            float v[9];
#pragma unroll
            for (int t = 0; t < 9; t++) v[t] = sm[ic * 9 + t];
            float s9 = 0.f, va[3] = {0, 0, 0}, vb[3] = {0, 0, 0};
#pragma unroll
            for (int a = 0; a < 3; a++)
#pragma unroll
                for (int bb = 0; bb < 3; bb++) {
                    float x = v[a * 3 + bb];
                    s9 += x; va[a] += x; vb[bb] += x;
                }
            g_Aall[(size_t)oc1 * K1 + ic] = __float2bfloat16(s9);
#pragma unroll
            for (int a = 0; a < 3; a++)
                g_Aall[(size_t)(512 + oc1 * 3 + a) * K1 + ic] = __float2bfloat16(va[a]);
#pragma unroll
            for (int bb = 0; bb < 3; bb++)
                g_Aall[(size_t)(2048 + oc1 * 3 + bb) * K1 + ic] = __float2bfloat16(vb[bb]);
#pragma unroll
            for (int t = 0; t < 9; t++)
                g_Aall[(size_t)(3584 + oc1 * 9 + t) * K1 + ic] = __float2bfloat16(v[t]);
        }
    } else if (bid < XPACK_BLOCKS + 512 + B_) {
        __shared__ int msh[NPIX];
        int b = bid - (XPACK_BLOCKS + 512);
        for (int p = threadIdx.x; p < NPIX; p += 256) {
            int pi = p / 24, qj = p % 24;
            msh[p] = targets[b * 147456 + (pi * 16) * 384 + qj * 16];
        }
        __syncthreads();
        int l = threadIdx.x;
        if (l < NL) {
            int bl = b * NL + l;
            int base = bl * PL_STRIDE;
            int cnt = 0;
            for (int p = 0; p < NPIX; p++)
                if (msh[p] == l) g_plist[base + cnt++] = (unsigned short)p;
            g_cnt[bl] = cnt;
            if (cnt & 1) g_plist[base + cnt] = 0xFFFF;   // pad to even
        }
    } else {
        __shared__ float tile[32][33];
        int t = bid - (XPACK_BLOCKS + 512 + B_);
        int b = t / (19 * 24);
        int r0 = t % (19 * 24);
        int s0 = (r0 % 19) * 32, c0 = (r0 / 19) * 32;
        int tx = threadIdx.x & 31, ty = threadIdx.x >> 5;
        for (int r = ty; r < 32; r += 8) {
            int s = s0 + tx;
            if (s < 577) tile[r][tx] = noise[(size_t)b * 443136 + (c0 + r) * 577 + s];
        }
        __syncthreads();
        for (int r = ty; r < 32; r += 8) {
            int s = s0 + r;
            if (s < 577) out_img[(size_t)s * (B_ * 768) + b * 768 + c0 + tx] = tile[tx][r];
        }
    }
}

// ---------------- GEMM core (BK=64, 2-stage, frag double-buffer) ----------------
#define RSTRIDE 144
#define A_ROWS  128
#define B_ROWS  64
#define BUFSZ   ((A_ROWS + B_ROWS) * RSTRIDE)   // 27648
#define SMEM_SZ (2 * BUFSZ)                     // 55296

template <typename OutT>
__device__ __forceinline__ void gemm_core(
    const __nv_bfloat16* __restrict__ A,
    const __nv_bfloat16* __restrict__ B,
    OutT* __restrict__ C,
    int ldk, int ktiles, int ldC, uint32_t sbase)
{
    const int tid = threadIdx.x;
    const int lane = tid & 31, wid = tid >> 5;
    const int wm = wid & 3, wn = wid >> 2;

    float acc[2][4][4];
#pragma unroll
    for (int i = 0; i < 2; i++)
#pragma unroll
        for (int j = 0; j < 4; j++)
#pragma unroll
            for (int q = 0; q < 4; q++) acc[i][j][q] = 0.f;

    auto load_tile = [&](int buf, int t) {
        uint32_t s = sbase + buf * BUFSZ;
        int k = t * 64;
#pragma unroll
        for (int i = 0; i < 6; i++) {
            int ch = tid + i * 256;
            int isB = ch >> 10;
            int row = (ch >> 3) & (isB ? 63 : 127);
            int c8 = ch & 7;
            uint32_t dst = s + isB * (A_ROWS * RSTRIDE) + row * RSTRIDE + c8 * 16;
            const __nv_bfloat16* src =
                (isB ? B + (size_t)row * ldk : A + (size_t)row * ldk) + k + c8 * 8;
            cpasync16(dst, src);
        }
    };

    load_tile(0, 0);
    CP_COMMIT();
    if (ktiles > 1) { load_tile(1, 1); }
    CP_COMMIT();

    const uint32_t rsel = lane & 15;
    const uint32_t chi = (lane >> 4) * 16;

    uint32_t aF[2][2][4];
    uint32_t bF[2][4][2];

    auto ld_frags = [&](int fb, uint32_t sA, uint32_t sB, int ks) {
        uint32_t colB = ks * 32 + chi;
#pragma unroll
        for (int mt = 0; mt < 2; mt++) {
            uint32_t addr = sA + (wm * 32 + mt * 16 + rsel) * RSTRIDE + colB;
            ldsm_x4(aF[fb][mt][0], aF[fb][mt][1], aF[fb][mt][2], aF[fb][mt][3], addr);
        }
#pragma unroll
        for (int p = 0; p < 2; p++) {
            uint32_t r0, r1, r2, r3;
            uint32_t addr = sB + (wn * 32 + p * 16 + rsel) * RSTRIDE + colB;
            ldsm_x4(r0, r1, r2, r3, addr);
            bF[fb][2 * p][0] = r0; bF[fb][2 * p][1] = r2;
            bF[fb][2 * p + 1][0] = r1; bF[fb][2 * p + 1][1] = r3;
        }
    };
    auto do_mma = [&](int fb) {
#pragma unroll
        for (int mt = 0; mt < 2; mt++)
#pragma unroll
            for (int nt = 0; nt < 4; nt++)
                mma_bf16(acc[mt][nt], aF[fb][mt], bF[fb][nt]);
    };

    for (int t = 0; t < ktiles; t++) {
        if (t + 1 < ktiles)
            asm volatile("cp.async.wait_group 1;\n" ::: "memory");
        else
            asm volatile("cp.async.wait_group 0;\n" ::: "memory");
        __syncthreads();

        int buf = t & 1;
        uint32_t sA = sbase + buf * BUFSZ;
        uint32_t sB = sA + A_ROWS * RSTRIDE;

        ld_frags(0, sA, sB, 0);
        ld_frags(1, sA, sB, 1);
        do_mma(0);
        ld_frags(0, sA, sB, 2);
        do_mma(1);
        ld_frags(1, sA, sB, 3);
        do_mma(0);
        __syncthreads();
        if (t + 2 < ktiles) {
            load_tile(buf, t + 2);
            CP_COMMIT();
        }
        do_mma(1);
    }

    const int mrow = lane >> 2, ncol = (lane & 3) * 2;
#pragma unroll
    for (int mt = 0; mt < 2; mt++)
#pragma unroll
        for (int nt = 0; nt < 4; nt++) {
            int m = wm * 32 + mt * 16 + mrow;
            int n = wn * 32 + nt * 8 + ncol;
            store_c(&C[(size_t)n * ldC + m],           acc[mt][nt][0]);
            store_c(&C[(size_t)(n + 1) * ldC + m],     acc[mt][nt][1]);
            store_c(&C[(size_t)n * ldC + m + 8],       acc[mt][nt][2]);
            store_c(&C[(size_t)(n + 1) * ldC + m + 8], acc[mt][nt][3]);
        }
}

// ---------------- GEMM1 (pure, 292 CTAs) ----------------
__global__ __launch_bounds__(256) void gemm1_k() {
    extern __shared__ __align__(128) char smem_raw[];
    uint32_t sbase = smem_u32(smem_raw);
    int bid = blockIdx.x;
    int seg = (bid < 28) ? 0 : (bid < 88) ? 1 : (bid < 148) ? 2 : 3;
    const int segStart[4] = {0, 28, 88, 148};
    const int segMt[4]    = {4, 12, 12, 36};
    const int segArow[4]  = {0, 512, 2048, 3584};
    const int segBrow[4]  = {0, 448, 768, 1088};
    const int segCoff[4]  = {P_II_OFF, P_EI_OFF, P_IE_OFF, P_EE_OFF};
    const int segLd[4]    = {512, 1536, 1536, 4608};
    int local = bid - segStart[seg];
    int bx = local % segMt[seg], by = local / segMt[seg];
    int m0 = bx * 128, n0 = by * 64;
    const __nv_bfloat16* A = g_Aall + (size_t)(segArow[seg] + m0) * K1;
    const __nv_bfloat16* B = g_Bx2 + (size_t)(segBrow[seg] + n0) * K1;
    __nv_bfloat16* C = g_Pcat + segCoff[seg] + (size_t)n0 * segLd[seg] + m0;
    gemm_core<__nv_bfloat16>(A, B, C, K1, K1 / 64, segLd[seg], sbase);
}

// GEMM2 split-K
__global__ __launch_bounds__(256) void gemm2_k() {
    extern __shared__ __align__(128) char smem_raw[];
    uint32_t sbase = smem_u32(smem_raw);
    int m0 = blockIdx.x * 128, n0 = blockIdx.y * 64;
    int z = blockIdx.z;
    int kt = K2 / KSPLIT / 64;   // 6
    const __nv_bfloat16* A = g_W2b + (size_t)m0 * K2 + z * kt * 64;
    const __nv_bfloat16* B = g_Tbb + (size_t)n0 * K2 + z * kt * 64;
    float* C = g_part + (size_t)z * NPAD * OC2 + (size_t)n0 * OC2 + m0;
    gemm_core<float>(A, B, C, K2, kt, OC2, sbase);
}

// ---------------- acc (342 blocks) + w2 cast (1152 blocks), 512 threads ----------------
#define ACCW2_BLOCKS (NBL + 1152)
__global__ __launch_bounds__(512) void acc_kernel(const float* __restrict__ b1,
                                                  const float4* __restrict__ w2) {
    int bid = blockIdx.x;
    if (bid >= NBL) {
        // w2 cast: 589824 uint2 elements over 1152 blocks x 512 threads
        int i = (bid - NBL) * 512 + threadIdx.x;
        float4 v = w2[i];
        __nv_bfloat162 lo, hi;
        lo.x = __float2bfloat16(v.x); lo.y = __float2bfloat16(v.y);
        hi.x = __float2bfloat16(v.z); hi.y = __float2bfloat16(v.w);
        uint2 o;
        o.x = *(uint32_t*)&lo; o.y = *(uint32_t*)&hi;
        ((uint2*)g_W2b)[i] = o;
        return;
    }

    const int bl = bid;
    const int b = bl / NL;
    const int oc1 = threadIdx.x;

    float T9a[9], T9b[9];
#pragma unroll
    for (int k = 0; k < 9; k++) { T9a[k] = 0.f; T9b[k] = 0.f; }

    const int cnt = g_cnt[bl];
    const unsigned short* plist = &g_plist[bl * PL_STRIDE];

    for (int i = 0; i < cnt; i += 2) {
        uint32_t pair = *(const uint32_t*)&plist[i];
        int pix0 = pair & 0xFFFF;
        int pix1 = pair >> 16;
        acc_pixel(b, oc1, pix0, T9a);
        if (pix1 != 0xFFFF) acc_pixel(b, oc1, pix1, T9b);
    }

    const float nrc[3] = {20.f, 24.f, 20.f};
    float bb1 = b1[oc1];
#pragma unroll
    for (int k = 0; k < 9; k++) {
        float t = (T9a[k] + T9b[k] + nrc[k / 3] * nrc[k % 3] * bb1) * (1.0f / 576.0f);
        g_Tbb[(size_t)bl * K2 + oc1 * 9 + k] = __float2bfloat16(t);
    }
}

// ---------------- fused reduce + expand (float4 stores) ----------------
__global__ __launch_bounds__(512) void expand2_k(const float* __restrict__ w3,
                                                 const float* __restrict__ b3,
                                                 const float* __restrict__ b2,
                                                 float4* __restrict__ out) {
    __shared__ float ssum[512];
    int bl = blockIdx.x;
    int b = bl / NL, l = bl % NL;
    int c = threadIdx.x;
    const int S = NPAD * OC2;
    float s = b2[c];
#pragma unroll
    for (int z = 0; z < KSPLIT; z++) s += g_part[(size_t)z * S + bl * OC2 + c];
    ssum[c] = s;
    __syncthreads();

    int c4 = threadIdx.x & 127;
    int grp = threadIdx.x >> 7;
    float4 sv = *(const float4*)&ssum[c4 * 4];
    size_t base4 = (((size_t)b * 77 * NL + l) * 512) / 4 + c4;
    for (int o = grp; o < 77; o += 4) {
        float w = __ldg(&w3[o]), bb = __ldg(&b3[o]);
        float4 r = make_float4(w * sv.x + bb, w * sv.y + bb, w * sv.z + bb, w * sv.w + bb);
        __stcs(&out[base4 + (size_t)o * NL * 128], r);
    }
}

// ---------------- launch ----------------
extern "C" void kernel_launch(void* const* d_in, const int* in_sizes, int n_in,
                              void* d_out, int out_size) {
    const float* noise   = (const float*)d_in[0];
    const int*   targets = (const int*)  d_in[1];
    const float* w1      = (const float*)d_in[2];
    const float* b1      = (const float*)d_in[3];
    const float* w2      = (const float*)d_in[4];
    const float* b2      = (const float*)d_in[5];
    const float* w3      = (const float*)d_in[6];
    const float* b3      = (const float*)d_in[7];
    float* out      = (float*)d_out;
    float* out_img  = out;
    float* out_text = out + IMG_ELEMS;

    cudaFuncSetAttribute(gemm1_k, cudaFuncAttributeMaxDynamicSharedMemorySize, SMEM_SZ);
    cudaFuncSetAttribute(gemm2_k, cudaFuncAttributeMaxDynamicSharedMemorySize, SMEM_SZ);

    prepA_k<<<PREPA_BLOCKS, 256>>>(noise, w1, targets, out_img);         // 1
    gemm1_k<<<292, 256, SMEM_SZ>>>();                                    // 2
    acc_kernel<<<ACCW2_BLOCKS, 512>>>(b1, (const float4*)w2);            // 3
    gemm2_k<<<dim3(OC2 / 128, NPAD / 64, KSPLIT), 256, SMEM_SZ>>>();     // 4 (profiled)
    expand2_k<<<NBL, 512>>>(w3, b3, b2, (float4*)out_text);              // 5
}

// round 16
// speedup vs baseline: 1.7191x; 1.0117x over previous
#include <cuda_runtime.h>
#include <cuda_bf16.h>
#include <cstdint>

// ---------------- problem constants ----------------
#define B_      2
#define NPIX    576
#define NL      171
#define NBL     342
#define NPAD    384
#define ICH     768
#define OC1     512
#define OC2     512
#define K1      768
#define K2      4608
#define KSPLIT  12
#define IMG_ELEMS  (577*B_*768)
#define TXT_ELEMS  (B_*77*NL*512)

// pixel classes: interior rows/cols = [5,18] (14), edge = 10
#define BX_ROWS 1344
#define AROWS   8192
#define P_II_OFF 0
#define P_EI_OFF 229376
#define P_IE_OFF 720896
#define P_EE_OFF 1212416
#define P_TOTAL  2392064
#define PL_STRIDE 580

// ---------------- scratch ----------------
__device__ __align__(128) __nv_bfloat16 g_Aall[(size_t)AROWS * K1];
__device__ __align__(128) __nv_bfloat16 g_Bx2[(size_t)BX_ROWS * K1];
__device__ __align__(128) __nv_bfloat16 g_Pcat[P_TOTAL];
__device__ __align__(128) __nv_bfloat16 g_W2b[OC2 * K2];
__device__ __align__(128) __nv_bfloat16 g_Tbb[NPAD * K2];
__device__ __align__(128) float         g_part[KSPLIT * NPAD * OC2];
__device__ unsigned short g_plist[NBL * PL_STRIDE];
__device__ int            g_cnt[NBL];

// ---------------- PTX helpers ----------------
__device__ __forceinline__ uint32_t smem_u32(const void* p) {
    uint32_t a;
    asm("{ .reg .u64 t; cvta.to.shared.u64 t, %1; cvt.u32.u64 %0, t; }" : "=r"(a) : "l"(p));
    return a;
}
__device__ __forceinline__ void cpasync16(uint32_t dst, const void* src) {
    asm volatile("cp.async.cg.shared.global [%0], [%1], 16;\n" :: "r"(dst), "l"(src));
}
#define CP_COMMIT() asm volatile("cp.async.commit_group;\n" ::: "memory")

__device__ __forceinline__ void ldsm_x4(uint32_t& r0, uint32_t& r1, uint32_t& r2,
                                        uint32_t& r3, uint32_t addr) {
    asm volatile("ldmatrix.sync.aligned.m8n8.x4.shared.b16 {%0,%1,%2,%3}, [%4];"
                 : "=r"(r0), "=r"(r1), "=r"(r2), "=r"(r3) : "r"(addr));
}
__device__ __forceinline__ void mma_bf16(float* c, const uint32_t* a, const uint32_t* b) {
    asm volatile("mma.sync.aligned.m16n8k16.row.col.f32.bf16.bf16.f32 "
                 "{%0,%1,%2,%3}, {%4,%5,%6,%7}, {%8,%9}, {%0,%1,%2,%3};"
                 : "+f"(c[0]), "+f"(c[1]), "+f"(c[2]), "+f"(c[3])
                 : "r"(a[0]), "r"(a[1]), "r"(a[2]), "r"(a[3]), "r"(b[0]), "r"(b[1]));
}
__device__ __forceinline__ void store_c(float* p, float v) { *p = v; }
__device__ __forceinline__ void store_c(__nv_bfloat16* p, float v) { *p = __float2bfloat16(v); }

__device__ __forceinline__ uint32_t pack_bf2(float a, float b) {
    __nv_bfloat162 v;
    v.x = __float2bfloat16(a);
    v.y = __float2bfloat16(b);
    return *(uint32_t*)&v;
}

// pixel -> B-matrix row (class-sorted layout)
__device__ __forceinline__ int browmap(int b, int pix) {
    int p = pix / 24, q = pix % 24;
    bool Ip = (p >= 5 && p <= 18), Iq = (q >= 5 && q <= 18);
    int rep = (p < 5) ? p : p - 14;
    int req = (q < 5) ? q : q - 14;
    if (Ip && Iq)  return        b * 196 + (p - 5) * 14 + (q - 5);
    if (!Ip && Iq) return 448 +  b * 140 + rep * 14 + (q - 5);
    if (Ip)        return 768 +  b * 140 + (p - 5) * 10 + req;
    return 1088 + b * 100 + rep * 10 + req;
}

// ---------------- acc per-pixel body ----------------
__device__ __forceinline__ void acc_pixel(int b, int oc1, int pix, float* T9) {
    const int lo[3][3] = {{0, 0, 1}, {0, 0, 1}, {3, 4, 5}};
    const int hi[3][3] = {{18, 19, 20}, {22, 23, 23}, {22, 23, 23}};
    int p = pix / 24, q = pix % 24;
    bool Ip = (p >= 5 && p <= 18), Iq = (q >= 5 && q <= 18);
    int rep = (p < 5) ? p : p - 14;
    int req = (q < 5) ? q : q - 14;

    if (Ip && Iq) {
        int slot = b * 196 + (p - 5) * 14 + (q - 5);
        float s = __bfloat162float(g_Pcat[P_II_OFF + (size_t)slot * 512 + oc1]);
#pragma unroll
        for (int k = 0; k < 9; k++) T9[k] += s;
    } else if (!Ip && Iq) {
        int slot = b * 140 + rep * 14 + (q - 5);
        const __nv_bfloat16* v = &g_Pcat[P_EI_OFF + (size_t)slot * 1536 + oc1 * 3];
        float ra[3];
#pragma unroll
        for (int a = 0; a < 3; a++) ra[a] = __bfloat162float(v[a]);
#pragma unroll
        for (int dr = 0; dr < 3; dr++) {
            float s = 0.f;
#pragma unroll
            for (int a = 0; a < 3; a++)
                if (p >= lo[dr][a] && p <= hi[dr][a]) s += ra[a];
            T9[dr * 3 + 0] += s; T9[dr * 3 + 1] += s; T9[dr * 3 + 2] += s;
        }
    } else if (Ip) {
        int slot = b * 140 + (p - 5) * 10 + req;
        const __nv_bfloat16* v = &g_Pcat[P_IE_OFF + (size_t)slot * 1536 + oc1 * 3];
        float rb[3];
#pragma unroll
        for (int bb = 0; bb < 3; bb++) rb[bb] = __bfloat162float(v[bb]);
#pragma unroll
        for (int dc = 0; dc < 3; dc++) {
            float s = 0.f;
#pragma unroll
            for (int bb = 0; bb < 3; bb++)
                if (q >= lo[dc][bb] && q <= hi[dc][bb]) s += rb[bb];
            T9[0 + dc] += s; T9[3 + dc] += s; T9[6 + dc] += s;
        }
    } else {
        int slot = b * 100 + rep * 10 + req;
        const __nv_bfloat16* v = &g_Pcat[P_EE_OFF + (size_t)slot * 4608 + oc1 * 9];
        float vv[9];
#pragma unroll
        for (int t = 0; t < 9; t++) vv[t] = __bfloat162float(v[t]);
        float rs[3][3];
#pragma unroll
        for (int dr = 0; dr < 3; dr++)
#pragma unroll
            for (int bb = 0; bb < 3; bb++) {
                float s = 0.f;
#pragma unroll
                for (int a = 0; a < 3; a++)
                    if (p >= lo[dr][a] && p <= hi[dr][a]) s += vv[a * 3 + bb];
                rs[dr][bb] = s;
            }
#pragma unroll
        for (int dr = 0; dr < 3; dr++)
#pragma unroll
            for (int dc = 0; dc < 3; dc++) {
                float s = 0.f;
#pragma unroll
                for (int bb = 0; bb < 3; bb++)
                    if (q >= lo[dc][bb] && q <= hi[dc][bb]) s += rs[dr][bb];
                T9[dr * 3 + dc] += s;
            }
    }
}

// ---------------- prep A: xpack (864) + w1r (512) + plist (2) + img transpose (912) ----------------
#define XPACK_BLOCKS (18 * 24 * 2)
#define IMG_BLOCKS (19 * 24 * 2)
#define PREPA_BLOCKS (XPACK_BLOCKS + 512 + B_ + IMG_BLOCKS)
__global__ __launch_bounds__(256) void prepA_k(const float* __restrict__ noise,
                                               const float* __restrict__ w1,
                                               const int* __restrict__ targets,
                                               float* __restrict__ out_img) {
    int bid = blockIdx.x;
    if (bid < XPACK_BLOCKS) {
        __shared__ float tile[32][33];
        int b = bid / (18 * 24);
        int r0 = bid % (18 * 24);
        int p0 = (r0 % 18) * 32, c0 = (r0 / 18) * 32;
        int tx = threadIdx.x & 31, ty = threadIdx.x >> 5;
        for (int r = ty; r < 32; r += 8)
            tile[r][tx] = noise[(size_t)b * 443136 + (c0 + r) * 577 + 1 + p0 + tx];
        __syncthreads();
        // paired-channel uint32 stores: 32 pixels x 16 channel-pairs
        for (int idx = threadIdx.x; idx < 512; idx += 256) {
            int r = idx >> 4;          // pixel within tile
            int cp = idx & 15;         // channel pair
            int dstrow = browmap(b, p0 + r);
            uint32_t v = pack_bf2(tile[2 * cp][r], tile[2 * cp + 1][r]);
            *(uint32_t*)&g_Bx2[(size_t)dstrow * K1 + c0 + 2 * cp] = v;
        }
    } else if (bid < XPACK_BLOCKS + 512) {
        __shared__ float sm[ICH * 9];
        int oc1 = bid - XPACK_BLOCKS;
        const float4* src = (const float4*)(w1 + (size_t)oc1 * ICH * 9);
        for (int i = threadIdx.x; i < ICH * 9 / 4; i += 256)
            ((float4*)sm)[i] = src[i];
        __syncthreads();
        // process ic pairs -> all stores are uint32
        for (int icp = threadIdx.x; icp < ICH / 2; icp += 256) {
            int ic = icp * 2;
            float v0[9], v1[9];
#pragma unroll
            for (int t = 0; t < 9; t++) { v0[t] = sm[ic * 9 + t]; v1[t] = sm[(ic + 1) * 9 + t]; }
            float s0 = 0.f, s1 = 0.f, a0[3] = {0,0,0}, a1[3] = {0,0,0}, b0[3] = {0,0,0}, b1[3] = {0,0,0};
#pragma unroll
            for (int a = 0; a < 3; a++)
#pragma unroll
                for (int bb = 0; bb < 3; bb++) {
                    float x0 = v0[a * 3 + bb], x1 = v1[a * 3 + bb];
                    s0 += x0; a0[a] += x0; b0[bb] += x0;
                    s1 += x1; a1[a] += x1; b1[bb] += x1;
                }
            *(uint32_t*)&g_Aall[(size_t)oc1 * K1 + ic] = pack_bf2(s0, s1);
#pragma unroll
            for (int a = 0; a < 3; a++)
                *(uint32_t*)&g_Aall[(size_t)(512 + oc1 * 3 + a) * K1 + ic] = pack_bf2(a0[a], a1[a]);
#pragma unroll
            for (int bb = 0; bb < 3; bb++)
                *(uint32_t*)&g_Aall[(size_t)(2048 + oc1 * 3 + bb) * K1 + ic] = pack_bf2(b0[bb], b1[bb]);
#pragma unroll
            for (int t = 0; t < 9; t++)
                *(uint32_t*)&g_Aall[(size_t)(3584 + oc1 * 9 + t) * K1 + ic] = pack_bf2(v0[t], v1[t]);
        }
    } else if (bid < XPACK_BLOCKS + 512 + B_) {
        __shared__ int msh[NPIX];
        int b = bid - (XPACK_BLOCKS + 512);
        for (int p = threadIdx.x; p < NPIX; p += 256) {
            int pi = p / 24, qj = p % 24;
            msh[p] = targets[b * 147456 + (pi * 16) * 384 + qj * 16];
        }
        __syncthreads();
        int l = threadIdx.x;
        if (l < NL) {
            int bl = b * NL + l;
            int base = bl * PL_STRIDE;
            int cnt = 0;
            for (int p = 0; p < NPIX; p++)
                if (msh[p] == l) g_plist[base + cnt++] = (unsigned short)p;
            g_cnt[bl] = cnt;
            if (cnt & 1) g_plist[base + cnt] = 0xFFFF;   // pad to even
        }
    } else {
        __shared__ float tile[32][33];
        int t = bid - (XPACK_BLOCKS + 512 + B_);
        int b = t / (19 * 24);
        int r0 = t % (19 * 24);
        int s0 = (r0 % 19) * 32, c0 = (r0 / 19) * 32;
        int tx = threadIdx.x & 31, ty = threadIdx.x >> 5;
        for (int r = ty; r < 32; r += 8) {
            int s = s0 + tx;
            if (s < 577) tile[r][tx] = noise[(size_t)b * 443136 + (c0 + r) * 577 + s];
        }
        __syncthreads();
        for (int r = ty; r < 32; r += 8) {
            int s = s0 + r;
            if (s < 577) out_img[(size_t)s * (B_ * 768) + b * 768 + c0 + tx] = tile[tx][r];
        }
    }
}

// ---------------- GEMM core (BK=64, 2-stage, frag double-buffer) ----------------
#define RSTRIDE 144
#define A_ROWS  128
#define B_ROWS  64
#define BUFSZ   ((A_ROWS + B_ROWS) * RSTRIDE)   // 27648
#define SMEM_SZ (2 * BUFSZ)                     // 55296

template <typename OutT>
__device__ __forceinline__ void gemm_core(
    const __nv_bfloat16* __restrict__ A,
    const __nv_bfloat16* __restrict__ B,
    OutT* __restrict__ C,
    int ldk, int ktiles, int ldC, uint32_t sbase)
{
    const int tid = threadIdx.x;
    const int lane = tid & 31, wid = tid >> 5;
    const int wm = wid & 3, wn = wid >> 2;

    float acc[2][4][4];
#pragma unroll
    for (int i = 0; i < 2; i++)
#pragma unroll
        for (int j = 0; j < 4; j++)
#pragma unroll
            for (int q = 0; q < 4; q++) acc[i][j][q] = 0.f;

    auto load_tile = [&](int buf, int t) {
        uint32_t s = sbase + buf * BUFSZ;
        int k = t * 64;
#pragma unroll
        for (int i = 0; i < 6; i++) {
            int ch = tid + i * 256;
            int isB = ch >> 10;
            int row = (ch >> 3) & (isB ? 63 : 127);
            int c8 = ch & 7;
            uint32_t dst = s + isB * (A_ROWS * RSTRIDE) + row * RSTRIDE + c8 * 16;
            const __nv_bfloat16* src =
                (isB ? B + (size_t)row * ldk : A + (size_t)row * ldk) + k + c8 * 8;
            cpasync16(dst, src);
        }
    };

    load_tile(0, 0);
    CP_COMMIT();
    if (ktiles > 1) { load_tile(1, 1); }
    CP_COMMIT();

    const uint32_t rsel = lane & 15;
    const uint32_t chi = (lane >> 4) * 16;

    uint32_t aF[2][2][4];
    uint32_t bF[2][4][2];

    auto ld_frags = [&](int fb, uint32_t sA, uint32_t sB, int ks) {
        uint32_t colB = ks * 32 + chi;
#pragma unroll
        for (int mt = 0; mt < 2; mt++) {
            uint32_t addr = sA + (wm * 32 + mt * 16 + rsel) * RSTRIDE + colB;
            ldsm_x4(aF[fb][mt][0], aF[fb][mt][1], aF[fb][mt][2], aF[fb][mt][3], addr);
        }
#pragma unroll
        for (int p = 0; p < 2; p++) {
            uint32_t r0, r1, r2, r3;
            uint32_t addr = sB + (wn * 32 + p * 16 + rsel) * RSTRIDE + colB;
            ldsm_x4(r0, r1, r2, r3, addr);
            bF[fb][2 * p][0] = r0; bF[fb][2 * p][1] = r2;
            bF[fb][2 * p + 1][0] = r1; bF[fb][2 * p + 1][1] = r3;
        }
    };
    auto do_mma = [&](int fb) {
#pragma unroll
        for (int mt = 0; mt < 2; mt++)
#pragma unroll
            for (int nt = 0; nt < 4; nt++)
                mma_bf16(acc[mt][nt], aF[fb][mt], bF[fb][nt]);
    };

    for (int t = 0; t < ktiles; t++) {
        if (t + 1 < ktiles)
            asm volatile("cp.async.wait_group 1;\n" ::: "memory");
        else
            asm volatile("cp.async.wait_group 0;\n" ::: "memory");
        __syncthreads();

        int buf = t & 1;
        uint32_t sA = sbase + buf * BUFSZ;
        uint32_t sB = sA + A_ROWS * RSTRIDE;

        ld_frags(0, sA, sB, 0);
        ld_frags(1, sA, sB, 1);
        do_mma(0);
        ld_frags(0, sA, sB, 2);
        do_mma(1);
        ld_frags(1, sA, sB, 3);
        do_mma(0);
        __syncthreads();
        if (t + 2 < ktiles) {
            load_tile(buf, t + 2);
            CP_COMMIT();
        }
        do_mma(1);
    }

    const int mrow = lane >> 2, ncol = (lane & 3) * 2;
#pragma unroll
    for (int mt = 0; mt < 2; mt++)
#pragma unroll
        for (int nt = 0; nt < 4; nt++) {
            int m = wm * 32 + mt * 16 + mrow;
            int n = wn * 32 + nt * 8 + ncol;
            store_c(&C[(size_t)n * ldC + m],           acc[mt][nt][0]);
            store_c(&C[(size_t)(n + 1) * ldC + m],     acc[mt][nt][1]);
            store_c(&C[(size_t)n * ldC + m + 8],       acc[mt][nt][2]);
            store_c(&C[(size_t)(n + 1) * ldC + m + 8], acc[mt][nt][3]);
        }
}

// ---------------- GEMM1 (pure, 292 CTAs) ----------------
__global__ __launch_bounds__(256) void gemm1_k() {
    extern __shared__ __align__(128) char smem_raw[];
    uint32_t sbase = smem_u32(smem_raw);
    int bid = blockIdx.x;
    int seg = (bid < 28) ? 0 : (bid < 88) ? 1 : (bid < 148) ? 2 : 3;
    const int segStart[4] = {0, 28, 88, 148};
    const int segMt[4]    = {4, 12, 12, 36};
    const int segArow[4]  = {0, 512, 2048, 3584};
    const int segBrow[4]  = {0, 448, 768, 1088};
    const int segCoff[4]  = {P_II_OFF, P_EI_OFF, P_IE_OFF, P_EE_OFF};
    const int segLd[4]    = {512, 1536, 1536, 4608};
    int local = bid - segStart[seg];
    int bx = local % segMt[seg], by = local / segMt[seg];
    int m0 = bx * 128, n0 = by * 64;
    const __nv_bfloat16* A = g_Aall + (size_t)(segArow[seg] + m0) * K1;
    const __nv_bfloat16* B = g_Bx2 + (size_t)(segBrow[seg] + n0) * K1;
    __nv_bfloat16* C = g_Pcat + segCoff[seg] + (size_t)n0 * segLd[seg] + m0;
    gemm_core<__nv_bfloat16>(A, B, C, K1, K1 / 64, segLd[seg], sbase);
}

// GEMM2 split-K
__global__ __launch_bounds__(256) void gemm2_k() {
    extern __shared__ __align__(128) char smem_raw[];
    uint32_t sbase = smem_u32(smem_raw);
    int m0 = blockIdx.x * 128, n0 = blockIdx.y * 64;
    int z = blockIdx.z;
    int kt = K2 / KSPLIT / 64;   // 6
    const __nv_bfloat16* A = g_W2b + (size_t)m0 * K2 + z * kt * 64;
    const __nv_bfloat16* B = g_Tbb + (size_t)n0 * K2 + z * kt * 64;
    float* C = g_part + (size_t)z * NPAD * OC2 + (size_t)n0 * OC2 + m0;
    gemm_core<float>(A, B, C, K2, kt, OC2, sbase);
}

// ---------------- acc (342 blocks) + w2 cast (1152 blocks), 512 threads ----------------
#define ACCW2_BLOCKS (NBL + 1152)
__global__ __launch_bounds__(512) void acc_kernel(const float* __restrict__ b1,
                                                  const float4* __restrict__ w2) {
    int bid = blockIdx.x;
    if (bid >= NBL) {
        int i = (bid - NBL) * 512 + threadIdx.x;
        float4 v = w2[i];
        uint2 o;
        o.x = pack_bf2(v.x, v.y);
        o.y = pack_bf2(v.z, v.w);
        ((uint2*)g_W2b)[i] = o;
        return;
    }

    const int bl = bid;
    const int b = bl / NL;
    const int oc1 = threadIdx.x;

    float T9a[9], T9b[9];
#pragma unroll
    for (int k = 0; k < 9; k++) { T9a[k] = 0.f; T9b[k] = 0.f; }

    const int cnt = g_cnt[bl];
    const unsigned short* plist = &g_plist[bl * PL_STRIDE];

    for (int i = 0; i < cnt; i += 2) {
        uint32_t pair = *(const uint32_t*)&plist[i];
        int pix0 = pair & 0xFFFF;
        int pix1 = pair >> 16;
        acc_pixel(b, oc1, pix0, T9a);
        if (pix1 != 0xFFFF) acc_pixel(b, oc1, pix1, T9b);
    }

    const float nrc[3] = {20.f, 24.f, 20.f};
    float bb1 = b1[oc1];
#pragma unroll
    for (int k = 0; k < 9; k++) {
        float t = (T9a[k] + T9b[k] + nrc[k / 3] * nrc[k % 3] * bb1) * (1.0f / 576.0f);
        g_Tbb[(size_t)bl * K2 + oc1 * 9 + k] = __float2bfloat16(t);
    }
}

// ---------------- fused reduce + expand (float4 stores) ----------------
__global__ __launch_bounds__(512) void expand2_k(const float* __restrict__ w3,
                                                 const float* __restrict__ b3,
                                                 const float* __restrict__ b2,
                                                 float4* __restrict__ out) {
    __shared__ float ssum[512];
    int bl = blockIdx.x;
    int b = bl / NL, l = bl % NL;
    int c = threadIdx.x;
    const int S = NPAD * OC2;
    float s = b2[c];
#pragma unroll
    for (int z = 0; z < KSPLIT; z++) s += g_part[(size_t)z * S + bl * OC2 + c];
    ssum[c] = s;
    __syncthreads();

    int c4 = threadIdx.x & 127;
    int grp = threadIdx.x >> 7;
    float4 sv = *(const float4*)&ssum[c4 * 4];
    size_t base4 = (((size_t)b * 77 * NL + l) * 512) / 4 + c4;
    for (int o = grp; o < 77; o += 4) {
        float w = __ldg(&w3[o]), bb = __ldg(&b3[o]);
        float4 r = make_float4(w * sv.x + bb, w * sv.y + bb, w * sv.z + bb, w * sv.w + bb);
        __stcs(&out[base4 + (size_t)o * NL * 128], r);
    }
}

// ---------------- launch ----------------
extern "C" void kernel_launch(void* const* d_in, const int* in_sizes, int n_in,
                              void* d_out, int out_size) {
    const float* noise   = (const float*)d_in[0];
    const int*   targets = (const int*)  d_in[1];
    const float* w1      = (const float*)d_in[2];
    const float* b1      = (const float*)d_in[3];
    const float* w2      = (const float*)d_in[4];
    const float* b2      = (const float*)d_in[5];
    const float* w3      = (const float*)d_in[6];
    const float* b3      = (const float*)d_in[7];
    float* out      = (float*)d_out;
    float* out_img  = out;
    float* out_text = out + IMG_ELEMS;

    cudaFuncSetAttribute(gemm1_k, cudaFuncAttributeMaxDynamicSharedMemorySize, SMEM_SZ);
    cudaFuncSetAttribute(gemm2_k, cudaFuncAttributeMaxDynamicSharedMemorySize, SMEM_SZ);

    prepA_k<<<PREPA_BLOCKS, 256>>>(noise, w1, targets, out_img);         // 1
    gemm1_k<<<292, 256, SMEM_SZ>>>();                                    // 2
    acc_kernel<<<ACCW2_BLOCKS, 512>>>(b1, (const float4*)w2);            // 3
    gemm2_k<<<dim3(OC2 / 128, NPAD / 64, KSPLIT), 256, SMEM_SZ>>>();     // 4 (profiled)
    expand2_k<<<NBL, 512>>>(w3, b3, b2, (float4*)out_text);              // 5
}